// round 11
// baseline (speedup 1.0000x reference)
#include <cuda_runtime.h>
#include <cuda_bf16.h>
#include <math.h>
#include <stdint.h>

// Problem constants
#define Bn   2
#define Ln   2048
#define Hn   16
#define KVn  4
#define Dn   128
#define HIDn 2048

// ---------------------------------------------------------------------------
// Portable tensor-core helpers (sm_80+ PTX only; harness ptxas targets sm_103
// without the 'a' feature set, so no tcgen05)
// ---------------------------------------------------------------------------
__device__ __forceinline__ uint32_t smem_to_u32(const void* p) {
    uint32_t a;
    asm("{ .reg .u64 t; cvta.to.shared.u64 t, %1; cvt.u32.u64 %0, t; }" : "=r"(a) : "l"(p));
    return a;
}
__device__ __forceinline__ void ldm_x4(uint32_t* r, uint32_t a) {
    asm volatile("ldmatrix.sync.aligned.m8n8.x4.shared.b16 {%0,%1,%2,%3}, [%4];"
        : "=r"(r[0]), "=r"(r[1]), "=r"(r[2]), "=r"(r[3]) : "r"(a));
}
__device__ __forceinline__ void ldm_x4t(uint32_t* r, uint32_t a) {
    asm volatile("ldmatrix.sync.aligned.m8n8.x4.trans.shared.b16 {%0,%1,%2,%3}, [%4];"
        : "=r"(r[0]), "=r"(r[1]), "=r"(r[2]), "=r"(r[3]) : "r"(a));
}
__device__ __forceinline__ void mma16816(float* c, const uint32_t* a, const uint32_t* b) {
    asm volatile("mma.sync.aligned.m16n8k16.row.col.f32.bf16.bf16.f32 "
        "{%0,%1,%2,%3}, {%4,%5,%6,%7}, {%8,%9}, {%0,%1,%2,%3};"
        : "+f"(c[0]), "+f"(c[1]), "+f"(c[2]), "+f"(c[3])
        : "r"(a[0]), "r"(a[1]), "r"(a[2]), "r"(a[3]), "r"(b[0]), "r"(b[1]));
}
__device__ __forceinline__ void cpasync16(uint32_t s, const void* g) {
    asm volatile("cp.async.cg.shared.global [%0], [%1], 16;" :: "r"(s), "l"(g));
}
#define CP_COMMIT() asm volatile("cp.async.commit_group;" ::: "memory")
#define CP_WAIT(n)  asm volatile("cp.async.wait_group %0;" :: "n"(n) : "memory")

__device__ __forceinline__ uint32_t pack_bf16(float x, float y) {
    __nv_bfloat162 h = __float22bfloat162_rn(make_float2(x, y));
    return *(uint32_t*)&h;
}
__device__ __forceinline__ void split2(float x, float y, uint32_t& hi, uint32_t& lo) {
    __nv_bfloat162 h = __float22bfloat162_rn(make_float2(x, y));
    float2 hf = __bfloat1622float2(h);
    hi = *(uint32_t*)&h;
    lo = pack_bf16(x - hf.x, y - hf.y);
}

// FFMA-pipe exp (avoids the MUFU throughput wall; valid for x <= 0)
__device__ __forceinline__ float fast_exp(float x) {
    const float L2E = 1.4426950408889634f;
    x = fmaxf(x, -80.0f);
    float t  = fmaf(x, L2E, 12582912.0f);
    int   n  = __float_as_int(t) - 0x4B400000;
    float f  = fmaf(x, L2E, -(t - 12582912.0f));
    float p  = 1.3333558e-3f;
    p = fmaf(p, f, 9.6181291e-3f);
    p = fmaf(p, f, 5.5504109e-2f);
    p = fmaf(p, f, 2.4022651e-1f);
    p = fmaf(p, f, 6.9314718e-1f);
    p = fmaf(p, f, 1.0f);
    return __int_as_float(__float_as_int(p) + (n << 23));
}

// ---------------------------------------------------------------------------
// Scratch
// ---------------------------------------------------------------------------
#define SPLITK 2

// split Q/K/V head-major (bf16 hi/lo; Q pre-scaled by D^-0.5)
__device__ __align__(1024) __nv_bfloat16 g_qhi[(size_t)Bn * Hn  * Ln * Dn];
__device__ __align__(1024) __nv_bfloat16 g_qlo[(size_t)Bn * Hn  * Ln * Dn];
__device__ __align__(1024) __nv_bfloat16 g_khi[(size_t)Bn * KVn * Ln * Dn];
__device__ __align__(1024) __nv_bfloat16 g_klo[(size_t)Bn * KVn * Ln * Dn];
__device__ __align__(1024) __nv_bfloat16 g_vhi[(size_t)Bn * KVn * Ln * Dn];
__device__ __align__(1024) __nv_bfloat16 g_vlo[(size_t)Bn * KVn * Ln * Dn];

// split-K attention partials
__device__ __align__(1024) float  g_Opart[(size_t)SPLITK * Bn * Ln * Hn * Dn];
__device__ __align__(1024) float2 g_ml[(size_t)SPLITK * Bn * Hn * Ln];

// split activations: hidden_states first; later overwritten by merged attn out
__device__ __align__(1024) __nv_bfloat16 g_Ahi[(size_t)Bn * Ln * HIDn];
__device__ __align__(1024) __nv_bfloat16 g_Alo[(size_t)Bn * Ln * HIDn];
__device__ __align__(1024) __nv_bfloat16 g_WqT_hi[(size_t)Hn * Dn * HIDn];
__device__ __align__(1024) __nv_bfloat16 g_WqT_lo[(size_t)Hn * Dn * HIDn];
__device__ __align__(1024) __nv_bfloat16 g_WkT_hi[(size_t)KVn * Dn * HIDn];
__device__ __align__(1024) __nv_bfloat16 g_WkT_lo[(size_t)KVn * Dn * HIDn];
__device__ __align__(1024) __nv_bfloat16 g_WvT_hi[(size_t)KVn * Dn * HIDn];
__device__ __align__(1024) __nv_bfloat16 g_WvT_lo[(size_t)KVn * Dn * HIDn];
__device__ __align__(1024) __nv_bfloat16 g_WoT_hi[(size_t)HIDn * Hn * Dn];
__device__ __align__(1024) __nv_bfloat16 g_WoT_lo[(size_t)HIDn * Hn * Dn];

// ---------------------------------------------------------------------------
// Split fp32 -> bf16 hi + lo (hidden states)
// ---------------------------------------------------------------------------
__global__ __launch_bounds__(256)
void split_kernel(const float* __restrict__ src)
{
    size_t i = ((size_t)blockIdx.x * 256 + threadIdx.x) * 4;
    float4 v = *(const float4*)&src[i];
    __nv_bfloat16 h0 = __float2bfloat16(v.x), h1 = __float2bfloat16(v.y);
    __nv_bfloat16 h2 = __float2bfloat16(v.z), h3 = __float2bfloat16(v.w);
    __nv_bfloat16 l0 = __float2bfloat16(v.x - __bfloat162float(h0));
    __nv_bfloat16 l1 = __float2bfloat16(v.y - __bfloat162float(h1));
    __nv_bfloat16 l2 = __float2bfloat16(v.z - __bfloat162float(h2));
    __nv_bfloat16 l3 = __float2bfloat16(v.w - __bfloat162float(h3));
    __nv_bfloat162* ph = (__nv_bfloat162*)&g_Ahi[i];
    __nv_bfloat162* pl = (__nv_bfloat162*)&g_Alo[i];
    ph[0] = __nv_bfloat162(h0, h1); ph[1] = __nv_bfloat162(h2, h3);
    pl[0] = __nv_bfloat162(l0, l1); pl[1] = __nv_bfloat162(l2, l3);
}

// ---------------------------------------------------------------------------
// One launch for all 4 weight transposes+splits.
// ---------------------------------------------------------------------------
__global__ __launch_bounds__(256)
void transpose_split_all(const float* __restrict__ Wq, const float* __restrict__ Wk,
                         const float* __restrict__ Wv, const float* __restrict__ Wo)
{
    const float* src;
    __nv_bfloat16 *dh, *dl;
    int N, c0;
    const int cb = blockIdx.x;
    if (cb < 64)       { src = Wq; dh = g_WqT_hi; dl = g_WqT_lo; N = Hn * Dn;  c0 = cb; }
    else if (cb < 80)  { src = Wk; dh = g_WkT_hi; dl = g_WkT_lo; N = KVn * Dn; c0 = cb - 64; }
    else if (cb < 96)  { src = Wv; dh = g_WvT_hi; dl = g_WvT_lo; N = KVn * Dn; c0 = cb - 80; }
    else               { src = Wo; dh = g_WoT_hi; dl = g_WoT_lo; N = HIDn;     c0 = cb - 96; }

    __shared__ float t[32][33];
    const int tx = threadIdx.x & 31, ty = threadIdx.x >> 5;
#pragma unroll
    for (int j = 0; j < 4; j++) {
        int k = blockIdx.y * 32 + ty + j * 8;
        t[ty + j * 8][tx] = src[(size_t)k * N + c0 * 32 + tx];
    }
    __syncthreads();
#pragma unroll
    for (int j = 0; j < 4; j++) {
        int n = c0 * 32 + ty + j * 8;
        int k = blockIdx.y * 32 + tx;
        float x = t[tx][ty + j * 8];
        __nv_bfloat16 hi = __float2bfloat16(x);
        __nv_bfloat16 lo = __float2bfloat16(x - __bfloat162float(hi));
        dh[(size_t)n * HIDn + k] = hi;
        dl[(size_t)n * HIDn + k] = lo;
    }
}

// ---------------------------------------------------------------------------
// mma.sync split-bf16 GEMM, 128x128 tile per CTA (unchanged).
// ---------------------------------------------------------------------------
#define KC      32
#define NKCH    (HIDn / KC)
#define ROW_B   80
#define TILE_B  (128 * ROW_B)
#define BUF_B   (4 * TILE_B)
#define MM_SMEM (2 * BUF_B)
#define CSTR    132

template <bool QKV>
__global__ __launch_bounds__(256, 2)
void mm_kernel(const float* __restrict__ cosb, const float* __restrict__ sinb,
               const float* __restrict__ qw, const float* __restrict__ kw,
               float* __restrict__ outp)
{
    extern __shared__ char smc[];
    const uint32_t sb = smem_to_u32(smc);
    float* Cs = (float*)smc;

    const int tid = threadIdx.x;
    const int lane = tid & 31;
    const int wid = tid >> 5;
    const int warp_m = wid >> 2;
    const int warp_n = wid & 3;
    const int m0 = blockIdx.y * 128;
    const int n0 = blockIdx.x * 128;

    const __nv_bfloat16 *Bhi, *Blo;
    int bcol = n0, sel = 0;
    if (QKV) {
        if (n0 < Hn * Dn)                { Bhi = g_WqT_hi; Blo = g_WqT_lo; sel = 0; bcol = n0; }
        else if (n0 < (Hn + KVn) * Dn)   { Bhi = g_WkT_hi; Blo = g_WkT_lo; sel = 1; bcol = n0 - Hn * Dn; }
        else                             { Bhi = g_WvT_hi; Blo = g_WvT_lo; sel = 2; bcol = n0 - (Hn + KVn) * Dn; }
    } else {
        Bhi = g_WoT_hi; Blo = g_WoT_lo; bcol = n0;
    }

    float acc[4][4][4];
#pragma unroll
    for (int i = 0; i < 4; i++)
#pragma unroll
        for (int j = 0; j < 4; j++)
#pragma unroll
            for (int r = 0; r < 4; r++) acc[i][j][r] = 0.0f;

    auto load_chunk = [&](int ck, int buf) {
        const int kh = ck * KC;
#pragma unroll
        for (int it = 0; it < 8; it++) {
            const int t   = it >> 1;
            const int c   = ((it & 1) << 8) + tid;
            const int row = c >> 2;
            const int seg = c & 3;
            const uint32_t sa = sb + buf * BUF_B + t * TILE_B + row * ROW_B + seg * 16;
            const __nv_bfloat16* g;
            if (t == 0)      g = g_Ahi + (size_t)(m0 + row) * HIDn;
            else if (t == 1) g = g_Alo + (size_t)(m0 + row) * HIDn;
            else if (t == 2) g = Bhi   + (size_t)(bcol + row) * HIDn;
            else             g = Blo   + (size_t)(bcol + row) * HIDn;
            cpasync16(sa, g + kh + seg * 8);
        }
    };

    const uint32_t aRow  = (uint32_t)(warp_m * 64 + (lane & 15)) * ROW_B + ((lane >> 4) << 4);
    const uint32_t bRow4 = (uint32_t)(warp_n * 32 + (lane & 7) + ((lane >> 4) << 3)) * ROW_B
                         + (((lane >> 3) & 1) << 4);

    load_chunk(0, 0);
    CP_COMMIT();

    for (int ck = 0; ck < NKCH; ck++) {
        const int buf = ck & 1;
        if (ck + 1 < NKCH) {
            load_chunk(ck + 1, buf ^ 1);
            CP_COMMIT();
            CP_WAIT(1);
        } else {
            CP_WAIT(0);
        }
        __syncthreads();

        const uint32_t base = sb + buf * BUF_B;
#pragma unroll
        for (int ks = 0; ks < 2; ks++) {
            const uint32_t ko = ks * 32;
            uint32_t aHi[16], aX[16], bX[8];
#pragma unroll
            for (int mt = 0; mt < 4; mt++)
                ldm_x4(&aHi[4 * mt], base + aRow + mt * (16 * ROW_B) + ko);
#pragma unroll
            for (int np = 0; np < 2; np++)
                ldm_x4(&bX[4 * np], base + 2 * TILE_B + bRow4 + np * (16 * ROW_B) + ko);
#pragma unroll
            for (int mt = 0; mt < 4; mt++)
#pragma unroll
                for (int nt = 0; nt < 4; nt++)
                    mma16816(acc[mt][nt], &aHi[4 * mt], &bX[2 * nt]);
#pragma unroll
            for (int mt = 0; mt < 4; mt++)
                ldm_x4(&aX[4 * mt], base + TILE_B + aRow + mt * (16 * ROW_B) + ko);
#pragma unroll
            for (int mt = 0; mt < 4; mt++)
#pragma unroll
                for (int nt = 0; nt < 4; nt++)
                    mma16816(acc[mt][nt], &aX[4 * mt], &bX[2 * nt]);
#pragma unroll
            for (int np = 0; np < 2; np++)
                ldm_x4(&bX[4 * np], base + 3 * TILE_B + bRow4 + np * (16 * ROW_B) + ko);
#pragma unroll
            for (int mt = 0; mt < 4; mt++)
#pragma unroll
                for (int nt = 0; nt < 4; nt++)
                    mma16816(acc[mt][nt], &aHi[4 * mt], &bX[2 * nt]);
        }
        __syncthreads();
    }

    {
        const int rb = warp_m * 64 + (lane >> 2);
        const int cb = warp_n * 32 + (lane & 3) * 2;
#pragma unroll
        for (int mt = 0; mt < 4; mt++)
#pragma unroll
            for (int nt = 0; nt < 4; nt++) {
                const int r = rb + mt * 16, c = cb + nt * 8;
                *(float2*)&Cs[r * CSTR + c]       = make_float2(acc[mt][nt][0], acc[mt][nt][1]);
                *(float2*)&Cs[(r + 8) * CSTR + c] = make_float2(acc[mt][nt][2], acc[mt][nt][3]);
            }
    }
    __syncthreads();

    if (QKV) {
        if (sel != 2 && tid < 128) {
            const float* nw = (sel == 0) ? qw : kw;
            float* row = Cs + tid * CSTR;
            float ss = 0.0f;
#pragma unroll 16
            for (int d = 0; d < 128; d++) ss += row[d] * row[d];
            const float rr = rsqrtf(ss * (1.0f / Dn) + 1e-6f);
            const int m = m0 + tid;
            const int b = m >> 11;
            const int l = m & (Ln - 1);
            const float* cp = cosb + ((size_t)b * Ln + l) * Dn;
            const float* sp = sinb + ((size_t)b * Ln + l) * Dn;
            const float post = (sel == 0) ? 0.08838834764831845f : 1.0f;
#pragma unroll 8
            for (int d = 0; d < 64; d++) {
                const float a  = row[d]      * rr * nw[d];
                const float b2 = row[d + 64] * rr * nw[d + 64];
                row[d]      = (a * cp[d]       - b2 * sp[d])     * post;
                row[d + 64] = (b2 * cp[d + 64] + a * sp[d + 64]) * post;
            }
        }
        __syncthreads();

        __nv_bfloat16 *dh, *dl;
        int NH, hh;
        if (sel == 0)      { dh = g_qhi; dl = g_qlo; NH = Hn;  hh = bcol >> 7; }
        else if (sel == 1) { dh = g_khi; dl = g_klo; NH = KVn; hh = bcol >> 7; }
        else               { dh = g_vhi; dl = g_vlo; NH = KVn; hh = bcol >> 7; }
#pragma unroll
        for (int it = 0; it < 16; it++) {
            const int idx = it * 256 + tid;
            const int row = idx >> 5;
            const int seg = idx & 31;
            const float4 v = *(float4*)&Cs[row * CSTR + seg * 4];
            const int m = m0 + row;
            const int b = m >> 11;
            const int l = m & (Ln - 1);
            const size_t off = (((size_t)b * NH + hh) * Ln + l) * Dn + seg * 4;
            uint32_t h01, l01, h23, l23;
            split2(v.x, v.y, h01, l01);
            split2(v.z, v.w, h23, l23);
            uint2 hv = {h01, h23}, lv = {l01, l23};
            *(uint2*)&dh[off] = hv;
            *(uint2*)&dl[off] = lv;
        }
    } else {
#pragma unroll
        for (int it = 0; it < 16; it++) {
            const int idx = it * 256 + tid;
            const int row = idx >> 5;
            const int seg = idx & 31;
            const float4 v = *(float4*)&Cs[row * CSTR + seg * 4];
            *(float4*)&outp[(size_t)(m0 + row) * HIDn + n0 + seg * 4] = v;
        }
    }
}

// ---------------------------------------------------------------------------
// Tensor-core flash attention, split-K=2, 2 CTAs/SM.
// CTA: 4 warps / 128 threads, 64 queries, 32-key tiles (double-buffered).
// SMEM 104448 B -> two co-resident CTAs overlap softmax with MMA.
// ---------------------------------------------------------------------------
#define ASTR_B    272
#define QSUB_B    (64 * ASTR_B)            // 17408 per Q subtile
#define KSUB_B    (32 * ASTR_B)            // 8704 per KV subtile
#define KV_OFF    (2 * QSUB_B)             // 34816
#define KVBUF_B   (4 * KSUB_B)             // 34816
#define ATTN_SMEM (KV_OFF + 2 * KVBUF_B)   // 104448
#define KT_SPLIT  (Ln / 32 / SPLITK)       // 32 tiles of 32 keys per split

__global__ __launch_bounds__(128, 2)
void attn_kernel()
{
    extern __shared__ char sm[];
    const uint32_t sb = smem_to_u32(sm);
    const int tid = threadIdx.x, lane = tid & 31, wid = tid >> 5;
    const int qt = blockIdx.x, h = blockIdx.y;
    const int b  = blockIdx.z >> 1, kz = blockIdx.z & 1;
    const int g  = h >> 2;

    const __nv_bfloat16* Qh = g_qhi + (((size_t)b * Hn + h) * Ln + qt * 64) * Dn;
    const __nv_bfloat16* Ql = g_qlo + (((size_t)b * Hn + h) * Ln + qt * 64) * Dn;
    const __nv_bfloat16* Kh = g_khi + ((size_t)b * KVn + g) * Ln * Dn;
    const __nv_bfloat16* Kl = g_klo + ((size_t)b * KVn + g) * Ln * Dn;
    const __nv_bfloat16* Vh = g_vhi + ((size_t)b * KVn + g) * Ln * Dn;
    const __nv_bfloat16* Vl = g_vlo + ((size_t)b * KVn + g) * Ln * Dn;

    // load Q hi/lo (64 x 128 bf16 each)
#pragma unroll
    for (int it = 0; it < 16; it++) {
        const int idx = it * 128 + tid;         // 0..2047
        const int sub = idx >> 10;
        const int rem = idx & 1023;
        const int r   = rem >> 4;
        const int c   = rem & 15;
        const __nv_bfloat16* src = (sub == 0) ? Qh : Ql;
        cpasync16(sb + sub * QSUB_B + r * ASTR_B + c * 16, src + (size_t)r * Dn + c * 8);
    }

    auto load_kv = [&](int kt, int buf) {
#pragma unroll
        for (int it = 0; it < 16; it++) {
            const int idx = it * 128 + tid;     // 0..2047
            const int sub = idx >> 9;
            const int rem = idx & 511;
            const int r   = rem >> 4;
            const int c   = rem & 15;
            const __nv_bfloat16* src;
            if (sub == 0)      src = Kh;
            else if (sub == 1) src = Kl;
            else if (sub == 2) src = Vh;
            else               src = Vl;
            cpasync16(sb + KV_OFF + buf * KVBUF_B + sub * KSUB_B + r * ASTR_B + c * 16,
                      src + (size_t)(kt * 32 + r) * Dn + c * 8);
        }
    };

    const int KT0 = kz * KT_SPLIT;
    const int KT1 = KT0 + KT_SPLIT;
    load_kv(KT0, 0);
    CP_COMMIT();

    float o[16][4];
#pragma unroll
    for (int i = 0; i < 16; i++)
#pragma unroll
        for (int j = 0; j < 4; j++) o[i][j] = 0.0f;
    float mrow[2] = {-1e30f, -1e30f};
    float lrow[2] = {0.0f, 0.0f};

    const uint32_t aoffQ = (uint32_t)(wid * 16 + (lane & 15)) * ASTR_B + ((lane >> 4) << 4);
    const uint32_t boffK = (uint32_t)((lane & 7) + ((lane >> 4) << 3)) * ASTR_B
                         + (((lane >> 3) & 1) << 4);
    const uint32_t voffR = (uint32_t)((lane & 7) + (((lane >> 3) & 1) << 3)) * ASTR_B
                         + ((lane >> 4) << 4);

    for (int kt = KT0; kt < KT1; kt++) {
        const int buf = kt & 1;
        if (kt + 1 < KT1) {
            load_kv(kt + 1, buf ^ 1);
            CP_COMMIT();
            CP_WAIT(1);
        } else {
            CP_WAIT(0);
        }
        __syncthreads();

        const uint32_t kb = sb + KV_OFF + buf * KVBUF_B;

        // ---- S = Qhi*Khi + Qlo*Khi + Qhi*Klo  (16 x 32 per warp) ----
        float s[4][4];
#pragma unroll
        for (int i = 0; i < 4; i++)
#pragma unroll
            for (int j = 0; j < 4; j++) s[i][j] = 0.0f;

#pragma unroll
        for (int kk = 0; kk < 8; kk++) {
            uint32_t aH[4], aL[4], bb[8];
            ldm_x4(aH, sb + aoffQ + kk * 32);
            ldm_x4(aL, sb + QSUB_B + aoffQ + kk * 32);
#pragma unroll
            for (int p = 0; p < 2; p++)
                ldm_x4(&bb[4 * p], kb + boffK + p * (16 * ASTR_B) + kk * 32);
#pragma unroll
            for (int nt = 0; nt < 4; nt++) mma16816(s[nt], aH, &bb[2 * nt]);
#pragma unroll
            for (int nt = 0; nt < 4; nt++) mma16816(s[nt], aL, &bb[2 * nt]);
#pragma unroll
            for (int p = 0; p < 2; p++)
                ldm_x4(&bb[4 * p], kb + KSUB_B + boffK + p * (16 * ASTR_B) + kk * 32);
#pragma unroll
            for (int nt = 0; nt < 4; nt++) mma16816(s[nt], aH, &bb[2 * nt]);
        }

        // ---- online softmax (rows lane>>2 and +8; quad shuffles) ----
        float mx0 = -1e30f, mx1 = -1e30f;
#pragma unroll
        for (int nt = 0; nt < 4; nt++) {
            mx0 = fmaxf(mx0, fmaxf(s[nt][0], s[nt][1]));
            mx1 = fmaxf(mx1, fmaxf(s[nt][2], s[nt][3]));
        }
        mx0 = fmaxf(mx0, __shfl_xor_sync(0xffffffffu, mx0, 1));
        mx0 = fmaxf(mx0, __shfl_xor_sync(0xffffffffu, mx0, 2));
        mx1 = fmaxf(mx1, __shfl_xor_sync(0xffffffffu, mx1, 1));
        mx1 = fmaxf(mx1, __shfl_xor_sync(0xffffffffu, mx1, 2));
        const float mn0 = fmaxf(mrow[0], mx0);
        const float mn1 = fmaxf(mrow[1], mx1);
        const float cr0 = fast_exp(mrow[0] - mn0);
        const float cr1 = fast_exp(mrow[1] - mn1);
        mrow[0] = mn0; mrow[1] = mn1;

        float sm0 = 0.0f, sm1 = 0.0f;
#pragma unroll
        for (int nt = 0; nt < 4; nt++) {
            s[nt][0] = fast_exp(s[nt][0] - mn0);
            s[nt][1] = fast_exp(s[nt][1] - mn0);
            s[nt][2] = fast_exp(s[nt][2] - mn1);
            s[nt][3] = fast_exp(s[nt][3] - mn1);
            sm0 += s[nt][0] + s[nt][1];
            sm1 += s[nt][2] + s[nt][3];
        }
        sm0 += __shfl_xor_sync(0xffffffffu, sm0, 1);
        sm0 += __shfl_xor_sync(0xffffffffu, sm0, 2);
        sm1 += __shfl_xor_sync(0xffffffffu, sm1, 1);
        sm1 += __shfl_xor_sync(0xffffffffu, sm1, 2);
        lrow[0] = lrow[0] * cr0 + sm0;
        lrow[1] = lrow[1] * cr1 + sm1;
#pragma unroll
        for (int nt = 0; nt < 16; nt++) {
            o[nt][0] *= cr0; o[nt][1] *= cr0;
            o[nt][2] *= cr1; o[nt][3] *= cr1;
        }

        // ---- O += Phi*Vhi + Plo*Vhi + Phi*Vlo ----
#pragma unroll
        for (int kk = 0; kk < 2; kk++) {
            uint32_t pH[4], pL[4];
            split2(s[2 * kk][0],     s[2 * kk][1],     pH[0], pL[0]);
            split2(s[2 * kk][2],     s[2 * kk][3],     pH[1], pL[1]);
            split2(s[2 * kk + 1][0], s[2 * kk + 1][1], pH[2], pL[2]);
            split2(s[2 * kk + 1][2], s[2 * kk + 1][3], pH[3], pL[3]);

            uint32_t vv[32];
            const uint32_t vrow = kk * (16 * ASTR_B) + voffR;
#pragma unroll
            for (int p = 0; p < 8; p++)
                ldm_x4t(&vv[4 * p], kb + 2 * KSUB_B + vrow + p * 32);
#pragma unroll
            for (int nt = 0; nt < 16; nt++) mma16816(o[nt], pH, &vv[2 * nt]);
#pragma unroll
            for (int nt = 0; nt < 16; nt++) mma16816(o[nt], pL, &vv[2 * nt]);
#pragma unroll
            for (int p = 0; p < 8; p++)
                ldm_x4t(&vv[4 * p], kb + 3 * KSUB_B + vrow + p * 32);
#pragma unroll
            for (int nt = 0; nt < 16; nt++) mma16816(o[nt], pH, &vv[2 * nt]);
        }
        __syncthreads();
    }

    // ---- epilogue: write un-normalized partial O + (m,l) ----
    const int q0 = qt * 64 + wid * 16 + (lane >> 2);
    if ((lane & 3) == 0) {
        g_ml[(((size_t)kz * Bn + b) * Hn + h) * Ln + q0]     = make_float2(mrow[0], lrow[0]);
        g_ml[(((size_t)kz * Bn + b) * Hn + h) * Ln + q0 + 8] = make_float2(mrow[1], lrow[1]);
    }
    const size_t r0 = (((size_t)kz * Bn + b) * Ln + q0) * (Hn * Dn) + h * Dn;
    const size_t r1 = r0 + (size_t)8 * Hn * Dn;
#pragma unroll
    for (int nt = 0; nt < 16; nt++) {
        const int d = nt * 8 + (lane & 3) * 2;
        *(float2*)&g_Opart[r0 + d] = make_float2(o[nt][0], o[nt][1]);
        *(float2*)&g_Opart[r1 + d] = make_float2(o[nt][2], o[nt][3]);
    }
}

// ---------------------------------------------------------------------------
// Merge the SPLITK partials, normalize, emit split bf16 into g_Ahi/g_Alo.
// ---------------------------------------------------------------------------
__global__ __launch_bounds__(256)
void merge_kernel()
{
    const size_t gid = (size_t)blockIdx.x * 256 + threadIdx.x;
    const size_t e4 = gid * 4;
    const size_t row = e4 >> 7;
    const int hh = (int)(row & (Hn - 1));
    const size_t bl = row >> 4;
    const int l = (int)(bl & (Ln - 1));
    const int b = (int)(bl >> 11);

    const float2 ml0 = g_ml[(((size_t)0 * Bn + b) * Hn + hh) * Ln + l];
    const float2 ml1 = g_ml[(((size_t)1 * Bn + b) * Hn + hh) * Ln + l];
    const float ms = fmaxf(ml0.x, ml1.x);
    const float w0 = fast_exp(ml0.x - ms);
    const float w1 = fast_exp(ml1.x - ms);
    const float inv = 1.0f / (ml0.y * w0 + ml1.y * w1);
    const float f0 = w0 * inv, f1 = w1 * inv;

    const float4 vA = *(const float4*)&g_Opart[e4];
    const float4 vB = *(const float4*)&g_Opart[(size_t)Bn * Ln * Hn * Dn + e4];
    const float x0 = vA.x * f0 + vB.x * f1;
    const float x1 = vA.y * f0 + vB.y * f1;
    const float x2 = vA.z * f0 + vB.z * f1;
    const float x3 = vA.w * f0 + vB.w * f1;

    uint32_t h01, l01, h23, l23;
    split2(x0, x1, h01, l01);
    split2(x2, x3, h23, l23);
    uint2 hv = {h01, h23}, lv = {l01, l23};
    *(uint2*)&g_Ahi[e4] = hv;
    *(uint2*)&g_Alo[e4] = lv;
}

// ---------------------------------------------------------------------------
extern "C" void kernel_launch(void* const* d_in, const int* in_sizes, int n_in,
                              void* d_out, int out_size)
{
    const float* hs = (const float*)d_in[0];
    const float* cs = (const float*)d_in[1];
    const float* sn = (const float*)d_in[2];
    const float* Wq = (const float*)d_in[3];
    const float* Wk = (const float*)d_in[4];
    const float* Wv = (const float*)d_in[5];
    const float* Wo = (const float*)d_in[6];
    const float* qw = (const float*)d_in[7];
    const float* kw = (const float*)d_in[8];
    float* out = (float*)d_out;

    cudaFuncSetAttribute(mm_kernel<true>,  cudaFuncAttributeMaxDynamicSharedMemorySize, MM_SMEM);
    cudaFuncSetAttribute(mm_kernel<false>, cudaFuncAttributeMaxDynamicSharedMemorySize, MM_SMEM);
    cudaFuncSetAttribute(attn_kernel, cudaFuncAttributeMaxDynamicSharedMemorySize, ATTN_SMEM);

    // Prep
    split_kernel<<<(Bn * Ln * HIDn) / 1024, 256>>>(hs);
    transpose_split_all<<<dim3(160, HIDn / 32), 256>>>(Wq, Wk, Wv, Wo);

    // Fused QKV projection
    mm_kernel<true><<<dim3((Hn + 2 * KVn) * Dn / 128, (Bn * Ln) / 128), 256, MM_SMEM>>>(
        cs, sn, qw, kw, nullptr);

    // Split-K flash attention (2 CTAs/SM) + merge
    attn_kernel<<<dim3(Ln / 64, Hn, Bn * SPLITK), 128, ATTN_SMEM>>>();
    merge_kernel<<<(Bn * Ln * Hn * Dn) / 1024, 256>>>();

    // Output projection
    mm_kernel<false><<<dim3(HIDn / 128, (Bn * Ln) / 128), 256, MM_SMEM>>>(
        nullptr, nullptr, nullptr, nullptr, out);
}

// round 12
// speedup vs baseline: 1.0292x; 1.0292x over previous
#include <cuda_runtime.h>
#include <cuda_bf16.h>
#include <math.h>
#include <stdint.h>

// Problem constants
#define Bn   2
#define Ln   2048
#define Hn   16
#define KVn  4
#define Dn   128
#define HIDn 2048

// ---------------------------------------------------------------------------
// Portable tensor-core helpers (sm_80+ PTX only; harness ptxas targets sm_103
// without the 'a' feature set, so no tcgen05)
// ---------------------------------------------------------------------------
__device__ __forceinline__ uint32_t smem_to_u32(const void* p) {
    uint32_t a;
    asm("{ .reg .u64 t; cvta.to.shared.u64 t, %1; cvt.u32.u64 %0, t; }" : "=r"(a) : "l"(p));
    return a;
}
__device__ __forceinline__ void ldm_x4(uint32_t* r, uint32_t a) {
    asm volatile("ldmatrix.sync.aligned.m8n8.x4.shared.b16 {%0,%1,%2,%3}, [%4];"
        : "=r"(r[0]), "=r"(r[1]), "=r"(r[2]), "=r"(r[3]) : "r"(a));
}
__device__ __forceinline__ void ldm_x4t(uint32_t* r, uint32_t a) {
    asm volatile("ldmatrix.sync.aligned.m8n8.x4.trans.shared.b16 {%0,%1,%2,%3}, [%4];"
        : "=r"(r[0]), "=r"(r[1]), "=r"(r[2]), "=r"(r[3]) : "r"(a));
}
__device__ __forceinline__ void mma16816(float* c, const uint32_t* a, const uint32_t* b) {
    asm volatile("mma.sync.aligned.m16n8k16.row.col.f32.bf16.bf16.f32 "
        "{%0,%1,%2,%3}, {%4,%5,%6,%7}, {%8,%9}, {%0,%1,%2,%3};"
        : "+f"(c[0]), "+f"(c[1]), "+f"(c[2]), "+f"(c[3])
        : "r"(a[0]), "r"(a[1]), "r"(a[2]), "r"(a[3]), "r"(b[0]), "r"(b[1]));
}
__device__ __forceinline__ void cpasync16(uint32_t s, const void* g) {
    asm volatile("cp.async.cg.shared.global [%0], [%1], 16;" :: "r"(s), "l"(g));
}
#define CP_COMMIT() asm volatile("cp.async.commit_group;" ::: "memory")
#define CP_WAIT(n)  asm volatile("cp.async.wait_group %0;" :: "n"(n) : "memory")

__device__ __forceinline__ uint32_t pack_bf16(float x, float y) {
    __nv_bfloat162 h = __float22bfloat162_rn(make_float2(x, y));
    return *(uint32_t*)&h;
}
__device__ __forceinline__ void split2(float x, float y, uint32_t& hi, uint32_t& lo) {
    __nv_bfloat162 h = __float22bfloat162_rn(make_float2(x, y));
    float2 hf = __bfloat1622float2(h);
    hi = *(uint32_t*)&h;
    lo = pack_bf16(x - hf.x, y - hf.y);
}

// FFMA-pipe exp (avoids the MUFU throughput wall; valid for x <= 0)
__device__ __forceinline__ float fast_exp(float x) {
    const float L2E = 1.4426950408889634f;
    x = fmaxf(x, -80.0f);
    float t  = fmaf(x, L2E, 12582912.0f);
    int   n  = __float_as_int(t) - 0x4B400000;
    float f  = fmaf(x, L2E, -(t - 12582912.0f));
    float p  = 1.3333558e-3f;
    p = fmaf(p, f, 9.6181291e-3f);
    p = fmaf(p, f, 5.5504109e-2f);
    p = fmaf(p, f, 2.4022651e-1f);
    p = fmaf(p, f, 6.9314718e-1f);
    p = fmaf(p, f, 1.0f);
    return __int_as_float(__float_as_int(p) + (n << 23));
}

// ---------------------------------------------------------------------------
// Scratch
// ---------------------------------------------------------------------------
#define SPLITK 2
#define KT_PER_SPLIT (Ln / 64 / SPLITK)   // 16 tiles of 64 keys

// split Q/K/V head-major (bf16 hi/lo; Q pre-scaled by D^-0.5)
__device__ __align__(1024) __nv_bfloat16 g_qhi[(size_t)Bn * Hn  * Ln * Dn];
__device__ __align__(1024) __nv_bfloat16 g_qlo[(size_t)Bn * Hn  * Ln * Dn];
__device__ __align__(1024) __nv_bfloat16 g_khi[(size_t)Bn * KVn * Ln * Dn];
__device__ __align__(1024) __nv_bfloat16 g_klo[(size_t)Bn * KVn * Ln * Dn];
__device__ __align__(1024) __nv_bfloat16 g_vhi[(size_t)Bn * KVn * Ln * Dn];
__device__ __align__(1024) __nv_bfloat16 g_vlo[(size_t)Bn * KVn * Ln * Dn];

// split-K attention partials
__device__ __align__(1024) float  g_Opart[(size_t)SPLITK * Bn * Ln * Hn * Dn];
__device__ __align__(1024) float2 g_ml[(size_t)SPLITK * Bn * Hn * Ln];

// split activations: hidden_states first; later overwritten by merged attn out
__device__ __align__(1024) __nv_bfloat16 g_Ahi[(size_t)Bn * Ln * HIDn];
__device__ __align__(1024) __nv_bfloat16 g_Alo[(size_t)Bn * Ln * HIDn];
__device__ __align__(1024) __nv_bfloat16 g_WqT_hi[(size_t)Hn * Dn * HIDn];
__device__ __align__(1024) __nv_bfloat16 g_WqT_lo[(size_t)Hn * Dn * HIDn];
__device__ __align__(1024) __nv_bfloat16 g_WkT_hi[(size_t)KVn * Dn * HIDn];
__device__ __align__(1024) __nv_bfloat16 g_WkT_lo[(size_t)KVn * Dn * HIDn];
__device__ __align__(1024) __nv_bfloat16 g_WvT_hi[(size_t)KVn * Dn * HIDn];
__device__ __align__(1024) __nv_bfloat16 g_WvT_lo[(size_t)KVn * Dn * HIDn];
__device__ __align__(1024) __nv_bfloat16 g_WoT_hi[(size_t)HIDn * Hn * Dn];
__device__ __align__(1024) __nv_bfloat16 g_WoT_lo[(size_t)HIDn * Hn * Dn];

// ---------------------------------------------------------------------------
// Fused prep: activation split + all 4 weight transposes in ONE launch.
// bid < 8192          : split hidden_states -> g_Ahi/g_Alo
// bid in [8192,18432) : transpose+split one 32x32 weight block
// ---------------------------------------------------------------------------
#define SPLIT_BLKS ((Bn * Ln * HIDn) / 1024)      // 8192
#define TRANS_BLKS (160 * (HIDn / 32))            // 10240

__global__ __launch_bounds__(256)
void prep_kernel(const float* __restrict__ hs,
                 const float* __restrict__ Wq, const float* __restrict__ Wk,
                 const float* __restrict__ Wv, const float* __restrict__ Wo)
{
    __shared__ float t[32][33];
    const int bid = blockIdx.x;

    if (bid < SPLIT_BLKS) {
        size_t i = ((size_t)bid * 256 + threadIdx.x) * 4;
        float4 v = *(const float4*)&hs[i];
        __nv_bfloat16 h0 = __float2bfloat16(v.x), h1 = __float2bfloat16(v.y);
        __nv_bfloat16 h2 = __float2bfloat16(v.z), h3 = __float2bfloat16(v.w);
        __nv_bfloat16 l0 = __float2bfloat16(v.x - __bfloat162float(h0));
        __nv_bfloat16 l1 = __float2bfloat16(v.y - __bfloat162float(h1));
        __nv_bfloat16 l2 = __float2bfloat16(v.z - __bfloat162float(h2));
        __nv_bfloat16 l3 = __float2bfloat16(v.w - __bfloat162float(h3));
        __nv_bfloat162* ph = (__nv_bfloat162*)&g_Ahi[i];
        __nv_bfloat162* pl = (__nv_bfloat162*)&g_Alo[i];
        ph[0] = __nv_bfloat162(h0, h1); ph[1] = __nv_bfloat162(h2, h3);
        pl[0] = __nv_bfloat162(l0, l1); pl[1] = __nv_bfloat162(l2, l3);
        return;
    }

    const int tb = bid - SPLIT_BLKS;
    const int cb = tb % 160;
    const int ky = tb / 160;

    const float* src;
    __nv_bfloat16 *dh, *dl;
    int N, c0;
    if (cb < 64)       { src = Wq; dh = g_WqT_hi; dl = g_WqT_lo; N = Hn * Dn;  c0 = cb; }
    else if (cb < 80)  { src = Wk; dh = g_WkT_hi; dl = g_WkT_lo; N = KVn * Dn; c0 = cb - 64; }
    else if (cb < 96)  { src = Wv; dh = g_WvT_hi; dl = g_WvT_lo; N = KVn * Dn; c0 = cb - 80; }
    else               { src = Wo; dh = g_WoT_hi; dl = g_WoT_lo; N = HIDn;     c0 = cb - 96; }

    const int tx = threadIdx.x & 31, ty = threadIdx.x >> 5;
#pragma unroll
    for (int j = 0; j < 4; j++) {
        int k = ky * 32 + ty + j * 8;
        t[ty + j * 8][tx] = src[(size_t)k * N + c0 * 32 + tx];
    }
    __syncthreads();
#pragma unroll
    for (int j = 0; j < 4; j++) {
        int n = c0 * 32 + ty + j * 8;
        int k = ky * 32 + tx;
        float x = t[tx][ty + j * 8];
        __nv_bfloat16 hi = __float2bfloat16(x);
        __nv_bfloat16 lo = __float2bfloat16(x - __bfloat162float(hi));
        dh[(size_t)n * HIDn + k] = hi;
        dl[(size_t)n * HIDn + k] = lo;
    }
}

// ---------------------------------------------------------------------------
// mma.sync split-bf16 GEMM, 128x128 tile per CTA.
// QKV==true : one launch for Q|K|V (N=3072 concat), fused norm+rope+scale,
//             emits split bf16 head-major.
// QKV==false: Wo GEMM, A = g_Ahi/lo (merged attn output), fp32 out.
// ---------------------------------------------------------------------------
#define KC      32
#define NKCH    (HIDn / KC)
#define ROW_B   80
#define TILE_B  (128 * ROW_B)
#define BUF_B   (4 * TILE_B)
#define MM_SMEM (2 * BUF_B)
#define CSTR    132

template <bool QKV>
__global__ __launch_bounds__(256, 2)
void mm_kernel(const float* __restrict__ cosb, const float* __restrict__ sinb,
               const float* __restrict__ qw, const float* __restrict__ kw,
               float* __restrict__ outp)
{
    extern __shared__ char smc[];
    const uint32_t sb = smem_to_u32(smc);
    float* Cs = (float*)smc;

    const int tid = threadIdx.x;
    const int lane = tid & 31;
    const int wid = tid >> 5;
    const int warp_m = wid >> 2;
    const int warp_n = wid & 3;
    const int m0 = blockIdx.y * 128;
    const int n0 = blockIdx.x * 128;

    const __nv_bfloat16 *Bhi, *Blo;
    int bcol = n0, sel = 0;
    if (QKV) {
        if (n0 < Hn * Dn)                { Bhi = g_WqT_hi; Blo = g_WqT_lo; sel = 0; bcol = n0; }
        else if (n0 < (Hn + KVn) * Dn)   { Bhi = g_WkT_hi; Blo = g_WkT_lo; sel = 1; bcol = n0 - Hn * Dn; }
        else                             { Bhi = g_WvT_hi; Blo = g_WvT_lo; sel = 2; bcol = n0 - (Hn + KVn) * Dn; }
    } else {
        Bhi = g_WoT_hi; Blo = g_WoT_lo; bcol = n0;
    }

    float acc[4][4][4];
#pragma unroll
    for (int i = 0; i < 4; i++)
#pragma unroll
        for (int j = 0; j < 4; j++)
#pragma unroll
            for (int r = 0; r < 4; r++) acc[i][j][r] = 0.0f;

    auto load_chunk = [&](int ck, int buf) {
        const int kh = ck * KC;
#pragma unroll
        for (int it = 0; it < 8; it++) {
            const int t   = it >> 1;
            const int c   = ((it & 1) << 8) + tid;
            const int row = c >> 2;
            const int seg = c & 3;
            const uint32_t sa = sb + buf * BUF_B + t * TILE_B + row * ROW_B + seg * 16;
            const __nv_bfloat16* g;
            if (t == 0)      g = g_Ahi + (size_t)(m0 + row) * HIDn;
            else if (t == 1) g = g_Alo + (size_t)(m0 + row) * HIDn;
            else if (t == 2) g = Bhi   + (size_t)(bcol + row) * HIDn;
            else             g = Blo   + (size_t)(bcol + row) * HIDn;
            cpasync16(sa, g + kh + seg * 8);
        }
    };

    const uint32_t aRow  = (uint32_t)(warp_m * 64 + (lane & 15)) * ROW_B + ((lane >> 4) << 4);
    const uint32_t bRow4 = (uint32_t)(warp_n * 32 + (lane & 7) + ((lane >> 4) << 3)) * ROW_B
                         + (((lane >> 3) & 1) << 4);

    load_chunk(0, 0);
    CP_COMMIT();

    for (int ck = 0; ck < NKCH; ck++) {
        const int buf = ck & 1;
        if (ck + 1 < NKCH) {
            load_chunk(ck + 1, buf ^ 1);
            CP_COMMIT();
            CP_WAIT(1);
        } else {
            CP_WAIT(0);
        }
        __syncthreads();

        const uint32_t base = sb + buf * BUF_B;
#pragma unroll
        for (int ks = 0; ks < 2; ks++) {
            const uint32_t ko = ks * 32;
            uint32_t aHi[16], aX[16], bX[8];
#pragma unroll
            for (int mt = 0; mt < 4; mt++)
                ldm_x4(&aHi[4 * mt], base + aRow + mt * (16 * ROW_B) + ko);
#pragma unroll
            for (int np = 0; np < 2; np++)
                ldm_x4(&bX[4 * np], base + 2 * TILE_B + bRow4 + np * (16 * ROW_B) + ko);
#pragma unroll
            for (int mt = 0; mt < 4; mt++)
#pragma unroll
                for (int nt = 0; nt < 4; nt++)
                    mma16816(acc[mt][nt], &aHi[4 * mt], &bX[2 * nt]);
#pragma unroll
            for (int mt = 0; mt < 4; mt++)
                ldm_x4(&aX[4 * mt], base + TILE_B + aRow + mt * (16 * ROW_B) + ko);
#pragma unroll
            for (int mt = 0; mt < 4; mt++)
#pragma unroll
                for (int nt = 0; nt < 4; nt++)
                    mma16816(acc[mt][nt], &aX[4 * mt], &bX[2 * nt]);
#pragma unroll
            for (int np = 0; np < 2; np++)
                ldm_x4(&bX[4 * np], base + 3 * TILE_B + bRow4 + np * (16 * ROW_B) + ko);
#pragma unroll
            for (int mt = 0; mt < 4; mt++)
#pragma unroll
                for (int nt = 0; nt < 4; nt++)
                    mma16816(acc[mt][nt], &aHi[4 * mt], &bX[2 * nt]);
        }
        __syncthreads();
    }

    {
        const int rb = warp_m * 64 + (lane >> 2);
        const int cb = warp_n * 32 + (lane & 3) * 2;
#pragma unroll
        for (int mt = 0; mt < 4; mt++)
#pragma unroll
            for (int nt = 0; nt < 4; nt++) {
                const int r = rb + mt * 16, c = cb + nt * 8;
                *(float2*)&Cs[r * CSTR + c]       = make_float2(acc[mt][nt][0], acc[mt][nt][1]);
                *(float2*)&Cs[(r + 8) * CSTR + c] = make_float2(acc[mt][nt][2], acc[mt][nt][3]);
            }
    }
    __syncthreads();

    if (QKV) {
        if (sel != 2 && tid < 128) {
            const float* nw = (sel == 0) ? qw : kw;
            float* row = Cs + tid * CSTR;
            float ss = 0.0f;
#pragma unroll 16
            for (int d = 0; d < 128; d++) ss += row[d] * row[d];
            const float rr = rsqrtf(ss * (1.0f / Dn) + 1e-6f);
            const int m = m0 + tid;
            const int b = m >> 11;
            const int l = m & (Ln - 1);
            const float* cp = cosb + ((size_t)b * Ln + l) * Dn;
            const float* sp = sinb + ((size_t)b * Ln + l) * Dn;
            const float post = (sel == 0) ? 0.08838834764831845f : 1.0f;
#pragma unroll 8
            for (int d = 0; d < 64; d++) {
                const float a  = row[d]      * rr * nw[d];
                const float b2 = row[d + 64] * rr * nw[d + 64];
                row[d]      = (a * cp[d]       - b2 * sp[d])     * post;
                row[d + 64] = (b2 * cp[d + 64] + a * sp[d + 64]) * post;
            }
        }
        __syncthreads();

        __nv_bfloat16 *dh, *dl;
        int NH, hh;
        if (sel == 0)      { dh = g_qhi; dl = g_qlo; NH = Hn;  hh = bcol >> 7; }
        else if (sel == 1) { dh = g_khi; dl = g_klo; NH = KVn; hh = bcol >> 7; }
        else               { dh = g_vhi; dl = g_vlo; NH = KVn; hh = bcol >> 7; }
#pragma unroll
        for (int it = 0; it < 16; it++) {
            const int idx = it * 256 + tid;
            const int row = idx >> 5;
            const int seg = idx & 31;
            const float4 v = *(float4*)&Cs[row * CSTR + seg * 4];
            const int m = m0 + row;
            const int b = m >> 11;
            const int l = m & (Ln - 1);
            const size_t off = (((size_t)b * NH + hh) * Ln + l) * Dn + seg * 4;
            uint32_t h01, l01, h23, l23;
            split2(v.x, v.y, h01, l01);
            split2(v.z, v.w, h23, l23);
            uint2 hv = {h01, h23}, lv = {l01, l23};
            *(uint2*)&dh[off] = hv;
            *(uint2*)&dl[off] = lv;
        }
    } else {
#pragma unroll
        for (int it = 0; it < 16; it++) {
            const int idx = it * 256 + tid;
            const int row = idx >> 5;
            const int seg = idx & 31;
            const float4 v = *(float4*)&Cs[row * CSTR + seg * 4];
            *(float4*)&outp[(size_t)(m0 + row) * HIDn + n0 + seg * 4] = v;
        }
    }
}

// ---------------------------------------------------------------------------
// Tensor-core flash attention, split-K over 2 CTAs per (qt,h,b).
// Round-9 configuration: 8 warps / 256 threads, 128 queries, 64-key tiles.
// (Round-11 4-warp variant regressed: same warps/SM, worse softmax ratio.)
// ---------------------------------------------------------------------------
#define ASTR_B   272
#define QSUB_B   (128 * ASTR_B)
#define KSUB_B   (64 * ASTR_B)
#define KV_OFF   (2 * QSUB_B)
#define KVBUF_B  (4 * KSUB_B)
#define ATTN_SMEM (KV_OFF + 2 * KVBUF_B)  // 208896

__global__ __launch_bounds__(256, 1)
void attn_kernel()
{
    extern __shared__ char sm[];
    const uint32_t sb = smem_to_u32(sm);
    const int tid = threadIdx.x, lane = tid & 31, wid = tid >> 5;
    const int qt = blockIdx.x, h = blockIdx.y;
    const int b  = blockIdx.z >> 1, kz = blockIdx.z & 1;
    const int g  = h >> 2;

    const __nv_bfloat16* Qh = g_qhi + (((size_t)b * Hn + h) * Ln + qt * 128) * Dn;
    const __nv_bfloat16* Ql = g_qlo + (((size_t)b * Hn + h) * Ln + qt * 128) * Dn;
    const __nv_bfloat16* Kh = g_khi + ((size_t)b * KVn + g) * Ln * Dn;
    const __nv_bfloat16* Kl = g_klo + ((size_t)b * KVn + g) * Ln * Dn;
    const __nv_bfloat16* Vh = g_vhi + ((size_t)b * KVn + g) * Ln * Dn;
    const __nv_bfloat16* Vl = g_vlo + ((size_t)b * KVn + g) * Ln * Dn;

#pragma unroll
    for (int it = 0; it < 16; it++) {
        const int sub = it >> 3;
        const int r   = (it & 7) * 16 + (tid >> 4);
        const int c   = tid & 15;
        const __nv_bfloat16* src = (sub == 0) ? Qh : Ql;
        cpasync16(sb + sub * QSUB_B + r * ASTR_B + c * 16, src + (size_t)r * Dn + c * 8);
    }

    auto load_kv = [&](int kt, int buf) {
#pragma unroll
        for (int it = 0; it < 16; it++) {
            const int sub = it >> 2;
            const int r   = (it & 3) * 16 + (tid >> 4);
            const int c   = tid & 15;
            const __nv_bfloat16* src;
            if (sub == 0)      src = Kh;
            else if (sub == 1) src = Kl;
            else if (sub == 2) src = Vh;
            else               src = Vl;
            cpasync16(sb + KV_OFF + buf * KVBUF_B + sub * KSUB_B + r * ASTR_B + c * 16,
                      src + (size_t)(kt * 64 + r) * Dn + c * 8);
        }
    };

    const int KT0 = kz * KT_PER_SPLIT;
    const int KT1 = KT0 + KT_PER_SPLIT;
    load_kv(KT0, 0);
    CP_COMMIT();

    float o[16][4];
#pragma unroll
    for (int i = 0; i < 16; i++)
#pragma unroll
        for (int j = 0; j < 4; j++) o[i][j] = 0.0f;
    float mrow[2] = {-1e30f, -1e30f};
    float lrow[2] = {0.0f, 0.0f};

    const uint32_t aoffQ = (uint32_t)(wid * 16 + (lane & 15)) * ASTR_B + ((lane >> 4) << 4);
    const uint32_t boffK = (uint32_t)((lane & 7) + ((lane >> 4) << 3)) * ASTR_B
                         + (((lane >> 3) & 1) << 4);
    const uint32_t voffR = (uint32_t)((lane & 7) + (((lane >> 3) & 1) << 3)) * ASTR_B
                         + ((lane >> 4) << 4);

    for (int kt = KT0; kt < KT1; kt++) {
        const int buf = kt & 1;
        if (kt + 1 < KT1) {
            load_kv(kt + 1, buf ^ 1);
            CP_COMMIT();
            CP_WAIT(1);
        } else {
            CP_WAIT(0);
        }
        __syncthreads();

        const uint32_t kb = sb + KV_OFF + buf * KVBUF_B;

        float s[8][4];
#pragma unroll
        for (int i = 0; i < 8; i++)
#pragma unroll
            for (int j = 0; j < 4; j++) s[i][j] = 0.0f;

#pragma unroll
        for (int kk = 0; kk < 8; kk++) {
            uint32_t aH[4], aL[4], bb[16];
            ldm_x4(aH, sb + aoffQ + kk * 32);
            ldm_x4(aL, sb + QSUB_B + aoffQ + kk * 32);
#pragma unroll
            for (int p = 0; p < 4; p++)
                ldm_x4(&bb[4 * p], kb + boffK + p * (16 * ASTR_B) + kk * 32);
#pragma unroll
            for (int nt = 0; nt < 8; nt++) mma16816(s[nt], aH, &bb[2 * nt]);
#pragma unroll
            for (int nt = 0; nt < 8; nt++) mma16816(s[nt], aL, &bb[2 * nt]);
#pragma unroll
            for (int p = 0; p < 4; p++)
                ldm_x4(&bb[4 * p], kb + KSUB_B + boffK + p * (16 * ASTR_B) + kk * 32);
#pragma unroll
            for (int nt = 0; nt < 8; nt++) mma16816(s[nt], aH, &bb[2 * nt]);
        }

        float mx0 = -1e30f, mx1 = -1e30f;
#pragma unroll
        for (int nt = 0; nt < 8; nt++) {
            mx0 = fmaxf(mx0, fmaxf(s[nt][0], s[nt][1]));
            mx1 = fmaxf(mx1, fmaxf(s[nt][2], s[nt][3]));
        }
        mx0 = fmaxf(mx0, __shfl_xor_sync(0xffffffffu, mx0, 1));
        mx0 = fmaxf(mx0, __shfl_xor_sync(0xffffffffu, mx0, 2));
        mx1 = fmaxf(mx1, __shfl_xor_sync(0xffffffffu, mx1, 1));
        mx1 = fmaxf(mx1, __shfl_xor_sync(0xffffffffu, mx1, 2));
        const float mn0 = fmaxf(mrow[0], mx0);
        const float mn1 = fmaxf(mrow[1], mx1);
        const float cr0 = fast_exp(mrow[0] - mn0);
        const float cr1 = fast_exp(mrow[1] - mn1);
        mrow[0] = mn0; mrow[1] = mn1;

        float sm0 = 0.0f, sm1 = 0.0f;
#pragma unroll
        for (int nt = 0; nt < 8; nt++) {
            s[nt][0] = fast_exp(s[nt][0] - mn0);
            s[nt][1] = fast_exp(s[nt][1] - mn0);
            s[nt][2] = fast_exp(s[nt][2] - mn1);
            s[nt][3] = fast_exp(s[nt][3] - mn1);
            sm0 += s[nt][0] + s[nt][1];
            sm1 += s[nt][2] + s[nt][3];
        }
        sm0 += __shfl_xor_sync(0xffffffffu, sm0, 1);
        sm0 += __shfl_xor_sync(0xffffffffu, sm0, 2);
        sm1 += __shfl_xor_sync(0xffffffffu, sm1, 1);
        sm1 += __shfl_xor_sync(0xffffffffu, sm1, 2);
        lrow[0] = lrow[0] * cr0 + sm0;
        lrow[1] = lrow[1] * cr1 + sm1;
#pragma unroll
        for (int nt = 0; nt < 16; nt++) {
            o[nt][0] *= cr0; o[nt][1] *= cr0;
            o[nt][2] *= cr1; o[nt][3] *= cr1;
        }

#pragma unroll
        for (int kk = 0; kk < 4; kk++) {
            uint32_t pH[4], pL[4];
            split2(s[2 * kk][0],     s[2 * kk][1],     pH[0], pL[0]);
            split2(s[2 * kk][2],     s[2 * kk][3],     pH[1], pL[1]);
            split2(s[2 * kk + 1][0], s[2 * kk + 1][1], pH[2], pL[2]);
            split2(s[2 * kk + 1][2], s[2 * kk + 1][3], pH[3], pL[3]);

            uint32_t vv[32];
            const uint32_t vrow = kk * (16 * ASTR_B) + voffR;
#pragma unroll
            for (int p = 0; p < 8; p++)
                ldm_x4t(&vv[4 * p], kb + 2 * KSUB_B + vrow + p * 32);
#pragma unroll
            for (int nt = 0; nt < 16; nt++) mma16816(o[nt], pH, &vv[2 * nt]);
#pragma unroll
            for (int nt = 0; nt < 16; nt++) mma16816(o[nt], pL, &vv[2 * nt]);
#pragma unroll
            for (int p = 0; p < 8; p++)
                ldm_x4t(&vv[4 * p], kb + 3 * KSUB_B + vrow + p * 32);
#pragma unroll
            for (int nt = 0; nt < 16; nt++) mma16816(o[nt], pH, &vv[2 * nt]);
        }
        __syncthreads();
    }

    // ---- epilogue: write un-normalized partial O + (m,l) ----
    const int q0 = qt * 128 + wid * 16 + (lane >> 2);
    if ((lane & 3) == 0) {
        g_ml[(((size_t)kz * Bn + b) * Hn + h) * Ln + q0]     = make_float2(mrow[0], lrow[0]);
        g_ml[(((size_t)kz * Bn + b) * Hn + h) * Ln + q0 + 8] = make_float2(mrow[1], lrow[1]);
    }
    const size_t r0 = (((size_t)kz * Bn + b) * Ln + q0) * (Hn * Dn) + h * Dn;
    const size_t r1 = r0 + (size_t)8 * Hn * Dn;
#pragma unroll
    for (int nt = 0; nt < 16; nt++) {
        const int d = nt * 8 + (lane & 3) * 2;
        *(float2*)&g_Opart[r0 + d] = make_float2(o[nt][0], o[nt][1]);
        *(float2*)&g_Opart[r1 + d] = make_float2(o[nt][2], o[nt][3]);
    }
}

// ---------------------------------------------------------------------------
// Merge the SPLITK partials, normalize, emit split bf16 into g_Ahi/g_Alo.
// ---------------------------------------------------------------------------
__global__ __launch_bounds__(256)
void merge_kernel()
{
    const size_t gid = (size_t)blockIdx.x * 256 + threadIdx.x;
    const size_t e4 = gid * 4;
    const size_t row = e4 >> 7;
    const int hh = (int)(row & (Hn - 1));
    const size_t bl = row >> 4;
    const int l = (int)(bl & (Ln - 1));
    const int b = (int)(bl >> 11);

    const float2 ml0 = g_ml[(((size_t)0 * Bn + b) * Hn + hh) * Ln + l];
    const float2 ml1 = g_ml[(((size_t)1 * Bn + b) * Hn + hh) * Ln + l];
    const float ms = fmaxf(ml0.x, ml1.x);
    const float w0 = fast_exp(ml0.x - ms);
    const float w1 = fast_exp(ml1.x - ms);
    const float inv = 1.0f / (ml0.y * w0 + ml1.y * w1);
    const float f0 = w0 * inv, f1 = w1 * inv;

    const float4 vA = *(const float4*)&g_Opart[e4];
    const float4 vB = *(const float4*)&g_Opart[(size_t)Bn * Ln * Hn * Dn + e4];
    const float x0 = vA.x * f0 + vB.x * f1;
    const float x1 = vA.y * f0 + vB.y * f1;
    const float x2 = vA.z * f0 + vB.z * f1;
    const float x3 = vA.w * f0 + vB.w * f1;

    uint32_t h01, l01, h23, l23;
    split2(x0, x1, h01, l01);
    split2(x2, x3, h23, l23);
    uint2 hv = {h01, h23}, lv = {l01, l23};
    *(uint2*)&g_Ahi[e4] = hv;
    *(uint2*)&g_Alo[e4] = lv;
}

// ---------------------------------------------------------------------------
extern "C" void kernel_launch(void* const* d_in, const int* in_sizes, int n_in,
                              void* d_out, int out_size)
{
    const float* hs = (const float*)d_in[0];
    const float* cs = (const float*)d_in[1];
    const float* sn = (const float*)d_in[2];
    const float* Wq = (const float*)d_in[3];
    const float* Wk = (const float*)d_in[4];
    const float* Wv = (const float*)d_in[5];
    const float* Wo = (const float*)d_in[6];
    const float* qw = (const float*)d_in[7];
    const float* kw = (const float*)d_in[8];
    float* out = (float*)d_out;

    cudaFuncSetAttribute(mm_kernel<true>,  cudaFuncAttributeMaxDynamicSharedMemorySize, MM_SMEM);
    cudaFuncSetAttribute(mm_kernel<false>, cudaFuncAttributeMaxDynamicSharedMemorySize, MM_SMEM);
    cudaFuncSetAttribute(attn_kernel, cudaFuncAttributeMaxDynamicSharedMemorySize, ATTN_SMEM);

    // Fused prep (activation split + weight transposes, one launch)
    prep_kernel<<<SPLIT_BLKS + TRANS_BLKS, 256>>>(hs, Wq, Wk, Wv, Wo);

    // Fused QKV projection
    mm_kernel<true><<<dim3((Hn + 2 * KVn) * Dn / 128, (Bn * Ln) / 128), 256, MM_SMEM>>>(
        cs, sn, qw, kw, nullptr);

    // Split-K flash attention (round-9 config) + merge
    attn_kernel<<<dim3(Ln / 128, Hn, Bn * SPLITK), 256, ATTN_SMEM>>>();
    merge_kernel<<<(Bn * Ln * Hn * Dn) / 1024, 256>>>();

    // Output projection
    mm_kernel<false><<<dim3(HIDn / 128, (Bn * Ln) / 128), 256, MM_SMEM>>>(
        nullptr, nullptr, nullptr, nullptr, out);
}

// round 13
// speedup vs baseline: 1.0397x; 1.0103x over previous
#include <cuda_runtime.h>
#include <cuda_bf16.h>
#include <math.h>
#include <stdint.h>

// Problem constants
#define Bn   2
#define Ln   2048
#define Hn   16
#define KVn  4
#define Dn   128
#define HIDn 2048

// ---------------------------------------------------------------------------
// Portable tensor-core helpers (sm_80+ PTX only; harness ptxas targets sm_103
// without the 'a' feature set, so no tcgen05)
// ---------------------------------------------------------------------------
__device__ __forceinline__ uint32_t smem_to_u32(const void* p) {
    uint32_t a;
    asm("{ .reg .u64 t; cvta.to.shared.u64 t, %1; cvt.u32.u64 %0, t; }" : "=r"(a) : "l"(p));
    return a;
}
__device__ __forceinline__ void ldm_x4(uint32_t* r, uint32_t a) {
    asm volatile("ldmatrix.sync.aligned.m8n8.x4.shared.b16 {%0,%1,%2,%3}, [%4];"
        : "=r"(r[0]), "=r"(r[1]), "=r"(r[2]), "=r"(r[3]) : "r"(a));
}
__device__ __forceinline__ void ldm_x4t(uint32_t* r, uint32_t a) {
    asm volatile("ldmatrix.sync.aligned.m8n8.x4.trans.shared.b16 {%0,%1,%2,%3}, [%4];"
        : "=r"(r[0]), "=r"(r[1]), "=r"(r[2]), "=r"(r[3]) : "r"(a));
}
__device__ __forceinline__ void mma16816(float* c, const uint32_t* a, const uint32_t* b) {
    asm volatile("mma.sync.aligned.m16n8k16.row.col.f32.bf16.bf16.f32 "
        "{%0,%1,%2,%3}, {%4,%5,%6,%7}, {%8,%9}, {%0,%1,%2,%3};"
        : "+f"(c[0]), "+f"(c[1]), "+f"(c[2]), "+f"(c[3])
        : "r"(a[0]), "r"(a[1]), "r"(a[2]), "r"(a[3]), "r"(b[0]), "r"(b[1]));
}
__device__ __forceinline__ void cpasync16(uint32_t s, const void* g) {
    asm volatile("cp.async.cg.shared.global [%0], [%1], 16;" :: "r"(s), "l"(g));
}
#define CP_COMMIT() asm volatile("cp.async.commit_group;" ::: "memory")
#define CP_WAIT(n)  asm volatile("cp.async.wait_group %0;" :: "n"(n) : "memory")

__device__ __forceinline__ uint32_t pack_bf16(float x, float y) {
    __nv_bfloat162 h = __float22bfloat162_rn(make_float2(x, y));
    return *(uint32_t*)&h;
}
__device__ __forceinline__ void split2(float x, float y, uint32_t& hi, uint32_t& lo) {
    __nv_bfloat162 h = __float22bfloat162_rn(make_float2(x, y));
    float2 hf = __bfloat1622float2(h);
    hi = *(uint32_t*)&h;
    lo = pack_bf16(x - hf.x, y - hf.y);
}

// FFMA-pipe exp (avoids the MUFU throughput wall; valid for x <= 0)
__device__ __forceinline__ float fast_exp(float x) {
    const float L2E = 1.4426950408889634f;
    x = fmaxf(x, -80.0f);
    float t  = fmaf(x, L2E, 12582912.0f);
    int   n  = __float_as_int(t) - 0x4B400000;
    float f  = fmaf(x, L2E, -(t - 12582912.0f));
    float p  = 1.3333558e-3f;
    p = fmaf(p, f, 9.6181291e-3f);
    p = fmaf(p, f, 5.5504109e-2f);
    p = fmaf(p, f, 2.4022651e-1f);
    p = fmaf(p, f, 6.9314718e-1f);
    p = fmaf(p, f, 1.0f);
    return __int_as_float(__float_as_int(p) + (n << 23));
}

// Fixed softmax offset: RMS-normed q,k (unit weights) give |s| <= 128*D^-0.5
// = 11.32 by Cauchy-Schwarz; RoPE preserves norms. M=24 leaves 12+ units of
// slack; exp(s-24) in [e^-36, e^-12] — no overflow/underflow, normalization
// cancels the constant exactly. Eliminates the online-max machinery.
#define FIXMAX 24.0f

// ---------------------------------------------------------------------------
// Scratch
// ---------------------------------------------------------------------------
#define SPLITK 2
#define KT_PER_SPLIT (Ln / 64 / SPLITK)   // 16 tiles of 64 keys

__device__ __align__(1024) __nv_bfloat16 g_qhi[(size_t)Bn * Hn  * Ln * Dn];
__device__ __align__(1024) __nv_bfloat16 g_qlo[(size_t)Bn * Hn  * Ln * Dn];
__device__ __align__(1024) __nv_bfloat16 g_khi[(size_t)Bn * KVn * Ln * Dn];
__device__ __align__(1024) __nv_bfloat16 g_klo[(size_t)Bn * KVn * Ln * Dn];
__device__ __align__(1024) __nv_bfloat16 g_vhi[(size_t)Bn * KVn * Ln * Dn];
__device__ __align__(1024) __nv_bfloat16 g_vlo[(size_t)Bn * KVn * Ln * Dn];

// split-K attention partials (fixed-max: only row sums, no maxima)
__device__ __align__(1024) float g_Opart[(size_t)SPLITK * Bn * Ln * Hn * Dn];
__device__ __align__(1024) float g_lsum [(size_t)SPLITK * Bn * Hn * Ln];

__device__ __align__(1024) __nv_bfloat16 g_Ahi[(size_t)Bn * Ln * HIDn];
__device__ __align__(1024) __nv_bfloat16 g_Alo[(size_t)Bn * Ln * HIDn];
__device__ __align__(1024) __nv_bfloat16 g_WqT_hi[(size_t)Hn * Dn * HIDn];
__device__ __align__(1024) __nv_bfloat16 g_WqT_lo[(size_t)Hn * Dn * HIDn];
__device__ __align__(1024) __nv_bfloat16 g_WkT_hi[(size_t)KVn * Dn * HIDn];
__device__ __align__(1024) __nv_bfloat16 g_WkT_lo[(size_t)KVn * Dn * HIDn];
__device__ __align__(1024) __nv_bfloat16 g_WvT_hi[(size_t)KVn * Dn * HIDn];
__device__ __align__(1024) __nv_bfloat16 g_WvT_lo[(size_t)KVn * Dn * HIDn];
__device__ __align__(1024) __nv_bfloat16 g_WoT_hi[(size_t)HIDn * Hn * Dn];
__device__ __align__(1024) __nv_bfloat16 g_WoT_lo[(size_t)HIDn * Hn * Dn];

// ---------------------------------------------------------------------------
// Fused prep: activation split + all 4 weight transposes in ONE launch.
// ---------------------------------------------------------------------------
#define SPLIT_BLKS ((Bn * Ln * HIDn) / 1024)      // 8192
#define TRANS_BLKS (160 * (HIDn / 32))            // 10240

__global__ __launch_bounds__(256)
void prep_kernel(const float* __restrict__ hs,
                 const float* __restrict__ Wq, const float* __restrict__ Wk,
                 const float* __restrict__ Wv, const float* __restrict__ Wo)
{
    __shared__ float t[32][33];
    const int bid = blockIdx.x;

    if (bid < SPLIT_BLKS) {
        size_t i = ((size_t)bid * 256 + threadIdx.x) * 4;
        float4 v = *(const float4*)&hs[i];
        __nv_bfloat16 h0 = __float2bfloat16(v.x), h1 = __float2bfloat16(v.y);
        __nv_bfloat16 h2 = __float2bfloat16(v.z), h3 = __float2bfloat16(v.w);
        __nv_bfloat16 l0 = __float2bfloat16(v.x - __bfloat162float(h0));
        __nv_bfloat16 l1 = __float2bfloat16(v.y - __bfloat162float(h1));
        __nv_bfloat16 l2 = __float2bfloat16(v.z - __bfloat162float(h2));
        __nv_bfloat16 l3 = __float2bfloat16(v.w - __bfloat162float(h3));
        __nv_bfloat162* ph = (__nv_bfloat162*)&g_Ahi[i];
        __nv_bfloat162* pl = (__nv_bfloat162*)&g_Alo[i];
        ph[0] = __nv_bfloat162(h0, h1); ph[1] = __nv_bfloat162(h2, h3);
        pl[0] = __nv_bfloat162(l0, l1); pl[1] = __nv_bfloat162(l2, l3);
        return;
    }

    const int tb = bid - SPLIT_BLKS;
    const int cb = tb % 160;
    const int ky = tb / 160;

    const float* src;
    __nv_bfloat16 *dh, *dl;
    int N, c0;
    if (cb < 64)       { src = Wq; dh = g_WqT_hi; dl = g_WqT_lo; N = Hn * Dn;  c0 = cb; }
    else if (cb < 80)  { src = Wk; dh = g_WkT_hi; dl = g_WkT_lo; N = KVn * Dn; c0 = cb - 64; }
    else if (cb < 96)  { src = Wv; dh = g_WvT_hi; dl = g_WvT_lo; N = KVn * Dn; c0 = cb - 80; }
    else               { src = Wo; dh = g_WoT_hi; dl = g_WoT_lo; N = HIDn;     c0 = cb - 96; }

    const int tx = threadIdx.x & 31, ty = threadIdx.x >> 5;
#pragma unroll
    for (int j = 0; j < 4; j++) {
        int k = ky * 32 + ty + j * 8;
        t[ty + j * 8][tx] = src[(size_t)k * N + c0 * 32 + tx];
    }
    __syncthreads();
#pragma unroll
    for (int j = 0; j < 4; j++) {
        int n = c0 * 32 + ty + j * 8;
        int k = ky * 32 + tx;
        float x = t[tx][ty + j * 8];
        __nv_bfloat16 hi = __float2bfloat16(x);
        __nv_bfloat16 lo = __float2bfloat16(x - __bfloat162float(hi));
        dh[(size_t)n * HIDn + k] = hi;
        dl[(size_t)n * HIDn + k] = lo;
    }
}

// ---------------------------------------------------------------------------
// mma.sync split-bf16 GEMM, 128x128 tile per CTA (unchanged).
// ---------------------------------------------------------------------------
#define KC      32
#define NKCH    (HIDn / KC)
#define ROW_B   80
#define TILE_B  (128 * ROW_B)
#define BUF_B   (4 * TILE_B)
#define MM_SMEM (2 * BUF_B)
#define CSTR    132

template <bool QKV>
__global__ __launch_bounds__(256, 2)
void mm_kernel(const float* __restrict__ cosb, const float* __restrict__ sinb,
               const float* __restrict__ qw, const float* __restrict__ kw,
               float* __restrict__ outp)
{
    extern __shared__ char smc[];
    const uint32_t sb = smem_to_u32(smc);
    float* Cs = (float*)smc;

    const int tid = threadIdx.x;
    const int lane = tid & 31;
    const int wid = tid >> 5;
    const int warp_m = wid >> 2;
    const int warp_n = wid & 3;
    const int m0 = blockIdx.y * 128;
    const int n0 = blockIdx.x * 128;

    const __nv_bfloat16 *Bhi, *Blo;
    int bcol = n0, sel = 0;
    if (QKV) {
        if (n0 < Hn * Dn)                { Bhi = g_WqT_hi; Blo = g_WqT_lo; sel = 0; bcol = n0; }
        else if (n0 < (Hn + KVn) * Dn)   { Bhi = g_WkT_hi; Blo = g_WkT_lo; sel = 1; bcol = n0 - Hn * Dn; }
        else                             { Bhi = g_WvT_hi; Blo = g_WvT_lo; sel = 2; bcol = n0 - (Hn + KVn) * Dn; }
    } else {
        Bhi = g_WoT_hi; Blo = g_WoT_lo; bcol = n0;
    }

    float acc[4][4][4];
#pragma unroll
    for (int i = 0; i < 4; i++)
#pragma unroll
        for (int j = 0; j < 4; j++)
#pragma unroll
            for (int r = 0; r < 4; r++) acc[i][j][r] = 0.0f;

    auto load_chunk = [&](int ck, int buf) {
        const int kh = ck * KC;
#pragma unroll
        for (int it = 0; it < 8; it++) {
            const int t   = it >> 1;
            const int c   = ((it & 1) << 8) + tid;
            const int row = c >> 2;
            const int seg = c & 3;
            const uint32_t sa = sb + buf * BUF_B + t * TILE_B + row * ROW_B + seg * 16;
            const __nv_bfloat16* g;
            if (t == 0)      g = g_Ahi + (size_t)(m0 + row) * HIDn;
            else if (t == 1) g = g_Alo + (size_t)(m0 + row) * HIDn;
            else if (t == 2) g = Bhi   + (size_t)(bcol + row) * HIDn;
            else             g = Blo   + (size_t)(bcol + row) * HIDn;
            cpasync16(sa, g + kh + seg * 8);
        }
    };

    const uint32_t aRow  = (uint32_t)(warp_m * 64 + (lane & 15)) * ROW_B + ((lane >> 4) << 4);
    const uint32_t bRow4 = (uint32_t)(warp_n * 32 + (lane & 7) + ((lane >> 4) << 3)) * ROW_B
                         + (((lane >> 3) & 1) << 4);

    load_chunk(0, 0);
    CP_COMMIT();

    for (int ck = 0; ck < NKCH; ck++) {
        const int buf = ck & 1;
        if (ck + 1 < NKCH) {
            load_chunk(ck + 1, buf ^ 1);
            CP_COMMIT();
            CP_WAIT(1);
        } else {
            CP_WAIT(0);
        }
        __syncthreads();

        const uint32_t base = sb + buf * BUF_B;
#pragma unroll
        for (int ks = 0; ks < 2; ks++) {
            const uint32_t ko = ks * 32;
            uint32_t aHi[16], aX[16], bX[8];
#pragma unroll
            for (int mt = 0; mt < 4; mt++)
                ldm_x4(&aHi[4 * mt], base + aRow + mt * (16 * ROW_B) + ko);
#pragma unroll
            for (int np = 0; np < 2; np++)
                ldm_x4(&bX[4 * np], base + 2 * TILE_B + bRow4 + np * (16 * ROW_B) + ko);
#pragma unroll
            for (int mt = 0; mt < 4; mt++)
#pragma unroll
                for (int nt = 0; nt < 4; nt++)
                    mma16816(acc[mt][nt], &aHi[4 * mt], &bX[2 * nt]);
#pragma unroll
            for (int mt = 0; mt < 4; mt++)
                ldm_x4(&aX[4 * mt], base + TILE_B + aRow + mt * (16 * ROW_B) + ko);
#pragma unroll
            for (int mt = 0; mt < 4; mt++)
#pragma unroll
                for (int nt = 0; nt < 4; nt++)
                    mma16816(acc[mt][nt], &aX[4 * mt], &bX[2 * nt]);
#pragma unroll
            for (int np = 0; np < 2; np++)
                ldm_x4(&bX[4 * np], base + 3 * TILE_B + bRow4 + np * (16 * ROW_B) + ko);
#pragma unroll
            for (int mt = 0; mt < 4; mt++)
#pragma unroll
                for (int nt = 0; nt < 4; nt++)
                    mma16816(acc[mt][nt], &aHi[4 * mt], &bX[2 * nt]);
        }
        __syncthreads();
    }

    {
        const int rb = warp_m * 64 + (lane >> 2);
        const int cb = warp_n * 32 + (lane & 3) * 2;
#pragma unroll
        for (int mt = 0; mt < 4; mt++)
#pragma unroll
            for (int nt = 0; nt < 4; nt++) {
                const int r = rb + mt * 16, c = cb + nt * 8;
                *(float2*)&Cs[r * CSTR + c]       = make_float2(acc[mt][nt][0], acc[mt][nt][1]);
                *(float2*)&Cs[(r + 8) * CSTR + c] = make_float2(acc[mt][nt][2], acc[mt][nt][3]);
            }
    }
    __syncthreads();

    if (QKV) {
        if (sel != 2 && tid < 128) {
            const float* nw = (sel == 0) ? qw : kw;
            float* row = Cs + tid * CSTR;
            float ss = 0.0f;
#pragma unroll 16
            for (int d = 0; d < 128; d++) ss += row[d] * row[d];
            const float rr = rsqrtf(ss * (1.0f / Dn) + 1e-6f);
            const int m = m0 + tid;
            const int b = m >> 11;
            const int l = m & (Ln - 1);
            const float* cp = cosb + ((size_t)b * Ln + l) * Dn;
            const float* sp = sinb + ((size_t)b * Ln + l) * Dn;
            const float post = (sel == 0) ? 0.08838834764831845f : 1.0f;
#pragma unroll 8
            for (int d = 0; d < 64; d++) {
                const float a  = row[d]      * rr * nw[d];
                const float b2 = row[d + 64] * rr * nw[d + 64];
                row[d]      = (a * cp[d]       - b2 * sp[d])     * post;
                row[d + 64] = (b2 * cp[d + 64] + a * sp[d + 64]) * post;
            }
        }
        __syncthreads();

        __nv_bfloat16 *dh, *dl;
        int NH, hh;
        if (sel == 0)      { dh = g_qhi; dl = g_qlo; NH = Hn;  hh = bcol >> 7; }
        else if (sel == 1) { dh = g_khi; dl = g_klo; NH = KVn; hh = bcol >> 7; }
        else               { dh = g_vhi; dl = g_vlo; NH = KVn; hh = bcol >> 7; }
#pragma unroll
        for (int it = 0; it < 16; it++) {
            const int idx = it * 256 + tid;
            const int row = idx >> 5;
            const int seg = idx & 31;
            const float4 v = *(float4*)&Cs[row * CSTR + seg * 4];
            const int m = m0 + row;
            const int b = m >> 11;
            const int l = m & (Ln - 1);
            const size_t off = (((size_t)b * NH + hh) * Ln + l) * Dn + seg * 4;
            uint32_t h01, l01, h23, l23;
            split2(v.x, v.y, h01, l01);
            split2(v.z, v.w, h23, l23);
            uint2 hv = {h01, h23}, lv = {l01, l23};
            *(uint2*)&dh[off] = hv;
            *(uint2*)&dl[off] = lv;
        }
    } else {
#pragma unroll
        for (int it = 0; it < 16; it++) {
            const int idx = it * 256 + tid;
            const int row = idx >> 5;
            const int seg = idx & 31;
            const float4 v = *(float4*)&Cs[row * CSTR + seg * 4];
            *(float4*)&outp[(size_t)(m0 + row) * HIDn + n0 + seg * 4] = v;
        }
    }
}

// ---------------------------------------------------------------------------
// Tensor-core flash attention, split-K=2, FIXED-MAX softmax.
// 8 warps / 256 threads, 128 queries, 64-key tiles (round-9 shape).
// No online max: p = exp(s - 24); per-thread sums, single final reduction.
// ---------------------------------------------------------------------------
#define ASTR_B   272
#define QSUB_B   (128 * ASTR_B)
#define KSUB_B   (64 * ASTR_B)
#define KV_OFF   (2 * QSUB_B)
#define KVBUF_B  (4 * KSUB_B)
#define ATTN_SMEM (KV_OFF + 2 * KVBUF_B)  // 208896

__global__ __launch_bounds__(256, 1)
void attn_kernel()
{
    extern __shared__ char sm[];
    const uint32_t sb = smem_to_u32(sm);
    const int tid = threadIdx.x, lane = tid & 31, wid = tid >> 5;
    const int qt = blockIdx.x, h = blockIdx.y;
    const int b  = blockIdx.z >> 1, kz = blockIdx.z & 1;
    const int g  = h >> 2;

    const __nv_bfloat16* Qh = g_qhi + (((size_t)b * Hn + h) * Ln + qt * 128) * Dn;
    const __nv_bfloat16* Ql = g_qlo + (((size_t)b * Hn + h) * Ln + qt * 128) * Dn;
    const __nv_bfloat16* Kh = g_khi + ((size_t)b * KVn + g) * Ln * Dn;
    const __nv_bfloat16* Kl = g_klo + ((size_t)b * KVn + g) * Ln * Dn;
    const __nv_bfloat16* Vh = g_vhi + ((size_t)b * KVn + g) * Ln * Dn;
    const __nv_bfloat16* Vl = g_vlo + ((size_t)b * KVn + g) * Ln * Dn;

#pragma unroll
    for (int it = 0; it < 16; it++) {
        const int sub = it >> 3;
        const int r   = (it & 7) * 16 + (tid >> 4);
        const int c   = tid & 15;
        const __nv_bfloat16* src = (sub == 0) ? Qh : Ql;
        cpasync16(sb + sub * QSUB_B + r * ASTR_B + c * 16, src + (size_t)r * Dn + c * 8);
    }

    auto load_kv = [&](int kt, int buf) {
#pragma unroll
        for (int it = 0; it < 16; it++) {
            const int sub = it >> 2;
            const int r   = (it & 3) * 16 + (tid >> 4);
            const int c   = tid & 15;
            const __nv_bfloat16* src;
            if (sub == 0)      src = Kh;
            else if (sub == 1) src = Kl;
            else if (sub == 2) src = Vh;
            else               src = Vl;
            cpasync16(sb + KV_OFF + buf * KVBUF_B + sub * KSUB_B + r * ASTR_B + c * 16,
                      src + (size_t)(kt * 64 + r) * Dn + c * 8);
        }
    };

    const int KT0 = kz * KT_PER_SPLIT;
    const int KT1 = KT0 + KT_PER_SPLIT;
    load_kv(KT0, 0);
    CP_COMMIT();

    float o[16][4];
#pragma unroll
    for (int i = 0; i < 16; i++)
#pragma unroll
        for (int j = 0; j < 4; j++) o[i][j] = 0.0f;
    float lsum0 = 0.0f, lsum1 = 0.0f;   // per-thread partial row sums

    const uint32_t aoffQ = (uint32_t)(wid * 16 + (lane & 15)) * ASTR_B + ((lane >> 4) << 4);
    const uint32_t boffK = (uint32_t)((lane & 7) + ((lane >> 4) << 3)) * ASTR_B
                         + (((lane >> 3) & 1) << 4);
    const uint32_t voffR = (uint32_t)((lane & 7) + (((lane >> 3) & 1) << 3)) * ASTR_B
                         + ((lane >> 4) << 4);

    for (int kt = KT0; kt < KT1; kt++) {
        const int buf = kt & 1;
        if (kt + 1 < KT1) {
            load_kv(kt + 1, buf ^ 1);
            CP_COMMIT();
            CP_WAIT(1);
        } else {
            CP_WAIT(0);
        }
        __syncthreads();

        const uint32_t kb = sb + KV_OFF + buf * KVBUF_B;

        float s[8][4];
#pragma unroll
        for (int i = 0; i < 8; i++)
#pragma unroll
            for (int j = 0; j < 4; j++) s[i][j] = 0.0f;

#pragma unroll
        for (int kk = 0; kk < 8; kk++) {
            uint32_t aH[4], aL[4], bb[16];
            ldm_x4(aH, sb + aoffQ + kk * 32);
            ldm_x4(aL, sb + QSUB_B + aoffQ + kk * 32);
#pragma unroll
            for (int p = 0; p < 4; p++)
                ldm_x4(&bb[4 * p], kb + boffK + p * (16 * ASTR_B) + kk * 32);
#pragma unroll
            for (int nt = 0; nt < 8; nt++) mma16816(s[nt], aH, &bb[2 * nt]);
#pragma unroll
            for (int nt = 0; nt < 8; nt++) mma16816(s[nt], aL, &bb[2 * nt]);
#pragma unroll
            for (int p = 0; p < 4; p++)
                ldm_x4(&bb[4 * p], kb + KSUB_B + boffK + p * (16 * ASTR_B) + kk * 32);
#pragma unroll
            for (int nt = 0; nt < 8; nt++) mma16816(s[nt], aH, &bb[2 * nt]);
        }

        // ---- fixed-max softmax: p = exp(s - 24); accumulate per-thread ----
#pragma unroll
        for (int nt = 0; nt < 8; nt++) {
            s[nt][0] = fast_exp(s[nt][0] - FIXMAX);
            s[nt][1] = fast_exp(s[nt][1] - FIXMAX);
            s[nt][2] = fast_exp(s[nt][2] - FIXMAX);
            s[nt][3] = fast_exp(s[nt][3] - FIXMAX);
            lsum0 += s[nt][0] + s[nt][1];
            lsum1 += s[nt][2] + s[nt][3];
        }

        // ---- O += Phi*Vhi + Plo*Vhi + Phi*Vlo ----
#pragma unroll
        for (int kk = 0; kk < 4; kk++) {
            uint32_t pH[4], pL[4];
            split2(s[2 * kk][0],     s[2 * kk][1],     pH[0], pL[0]);
            split2(s[2 * kk][2],     s[2 * kk][3],     pH[1], pL[1]);
            split2(s[2 * kk + 1][0], s[2 * kk + 1][1], pH[2], pL[2]);
            split2(s[2 * kk + 1][2], s[2 * kk + 1][3], pH[3], pL[3]);

            uint32_t vv[32];
            const uint32_t vrow = kk * (16 * ASTR_B) + voffR;
#pragma unroll
            for (int p = 0; p < 8; p++)
                ldm_x4t(&vv[4 * p], kb + 2 * KSUB_B + vrow + p * 32);
#pragma unroll
            for (int nt = 0; nt < 16; nt++) mma16816(o[nt], pH, &vv[2 * nt]);
#pragma unroll
            for (int nt = 0; nt < 16; nt++) mma16816(o[nt], pL, &vv[2 * nt]);
#pragma unroll
            for (int p = 0; p < 8; p++)
                ldm_x4t(&vv[4 * p], kb + 3 * KSUB_B + vrow + p * 32);
#pragma unroll
            for (int nt = 0; nt < 16; nt++) mma16816(o[nt], pH, &vv[2 * nt]);
        }
        __syncthreads();
    }

    // ---- single final row-sum reduction (quad shuffles) ----
    lsum0 += __shfl_xor_sync(0xffffffffu, lsum0, 1);
    lsum0 += __shfl_xor_sync(0xffffffffu, lsum0, 2);
    lsum1 += __shfl_xor_sync(0xffffffffu, lsum1, 1);
    lsum1 += __shfl_xor_sync(0xffffffffu, lsum1, 2);

    // ---- epilogue: write un-normalized partial O + row sums ----
    const int q0 = qt * 128 + wid * 16 + (lane >> 2);
    if ((lane & 3) == 0) {
        g_lsum[(((size_t)kz * Bn + b) * Hn + h) * Ln + q0]     = lsum0;
        g_lsum[(((size_t)kz * Bn + b) * Hn + h) * Ln + q0 + 8] = lsum1;
    }
    const size_t r0 = (((size_t)kz * Bn + b) * Ln + q0) * (Hn * Dn) + h * Dn;
    const size_t r1 = r0 + (size_t)8 * Hn * Dn;
#pragma unroll
    for (int nt = 0; nt < 16; nt++) {
        const int d = nt * 8 + (lane & 3) * 2;
        *(float2*)&g_Opart[r0 + d] = make_float2(o[nt][0], o[nt][1]);
        *(float2*)&g_Opart[r1 + d] = make_float2(o[nt][2], o[nt][3]);
    }
}

// ---------------------------------------------------------------------------
// Merge: shared fixed max means partials just add. Normalize, emit split bf16.
// ---------------------------------------------------------------------------
__global__ __launch_bounds__(256)
void merge_kernel()
{
    const size_t gid = (size_t)blockIdx.x * 256 + threadIdx.x;
    const size_t e4 = gid * 4;
    const size_t row = e4 >> 7;
    const int hh = (int)(row & (Hn - 1));
    const size_t bl = row >> 4;
    const int l = (int)(bl & (Ln - 1));
    const int b = (int)(bl >> 11);

    const float l0 = g_lsum[(((size_t)0 * Bn + b) * Hn + hh) * Ln + l];
    const float l1 = g_lsum[(((size_t)1 * Bn + b) * Hn + hh) * Ln + l];
    const float inv = 1.0f / (l0 + l1);

    const float4 vA = *(const float4*)&g_Opart[e4];
    const float4 vB = *(const float4*)&g_Opart[(size_t)Bn * Ln * Hn * Dn + e4];
    const float x0 = (vA.x + vB.x) * inv;
    const float x1 = (vA.y + vB.y) * inv;
    const float x2 = (vA.z + vB.z) * inv;
    const float x3 = (vA.w + vB.w) * inv;

    uint32_t h01, l01, h23, l23;
    split2(x0, x1, h01, l01);
    split2(x2, x3, h23, l23);
    uint2 hv = {h01, h23}, lv = {l01, l23};
    *(uint2*)&g_Ahi[e4] = hv;
    *(uint2*)&g_Alo[e4] = lv;
}

// ---------------------------------------------------------------------------
extern "C" void kernel_launch(void* const* d_in, const int* in_sizes, int n_in,
                              void* d_out, int out_size)
{
    const float* hs = (const float*)d_in[0];
    const float* cs = (const float*)d_in[1];
    const float* sn = (const float*)d_in[2];
    const float* Wq = (const float*)d_in[3];
    const float* Wk = (const float*)d_in[4];
    const float* Wv = (const float*)d_in[5];
    const float* Wo = (const float*)d_in[6];
    const float* qw = (const float*)d_in[7];
    const float* kw = (const float*)d_in[8];
    float* out = (float*)d_out;

    cudaFuncSetAttribute(mm_kernel<true>,  cudaFuncAttributeMaxDynamicSharedMemorySize, MM_SMEM);
    cudaFuncSetAttribute(mm_kernel<false>, cudaFuncAttributeMaxDynamicSharedMemorySize, MM_SMEM);
    cudaFuncSetAttribute(attn_kernel, cudaFuncAttributeMaxDynamicSharedMemorySize, ATTN_SMEM);

    // Fused prep
    prep_kernel<<<SPLIT_BLKS + TRANS_BLKS, 256>>>(hs, Wq, Wk, Wv, Wo);

    // Fused QKV projection
    mm_kernel<true><<<dim3((Hn + 2 * KVn) * Dn / 128, (Bn * Ln) / 128), 256, MM_SMEM>>>(
        cs, sn, qw, kw, nullptr);

    // Split-K flash attention (fixed-max softmax) + merge
    attn_kernel<<<dim3(Ln / 128, Hn, Bn * SPLITK), 256, ATTN_SMEM>>>();
    merge_kernel<<<(Bn * Ln * Hn * Dn) / 1024, 256>>>();

    // Output projection
    mm_kernel<false><<<dim3(HIDn / 128, (Bn * Ln) / 128), 256, MM_SMEM>>>(
        nullptr, nullptr, nullptr, nullptr, out);
}

// round 14
// speedup vs baseline: 1.2540x; 1.2061x over previous
#include <cuda_runtime.h>
#include <cuda_bf16.h>
#include <math.h>
#include <stdint.h>

// Problem constants
#define Bn   2
#define Ln   2048
#define Hn   16
#define KVn  4
#define Dn   128
#define HIDn 2048

// ---------------------------------------------------------------------------
// Portable tensor-core helpers (sm_80+ PTX only)
// ---------------------------------------------------------------------------
__device__ __forceinline__ uint32_t smem_to_u32(const void* p) {
    uint32_t a;
    asm("{ .reg .u64 t; cvta.to.shared.u64 t, %1; cvt.u32.u64 %0, t; }" : "=r"(a) : "l"(p));
    return a;
}
__device__ __forceinline__ void ldm_x4(uint32_t* r, uint32_t a) {
    asm volatile("ldmatrix.sync.aligned.m8n8.x4.shared.b16 {%0,%1,%2,%3}, [%4];"
        : "=r"(r[0]), "=r"(r[1]), "=r"(r[2]), "=r"(r[3]) : "r"(a));
}
__device__ __forceinline__ void ldm_x4t(uint32_t* r, uint32_t a) {
    asm volatile("ldmatrix.sync.aligned.m8n8.x4.trans.shared.b16 {%0,%1,%2,%3}, [%4];"
        : "=r"(r[0]), "=r"(r[1]), "=r"(r[2]), "=r"(r[3]) : "r"(a));
}
__device__ __forceinline__ void mma16816(float* c, const uint32_t* a, const uint32_t* b) {
    asm volatile("mma.sync.aligned.m16n8k16.row.col.f32.bf16.bf16.f32 "
        "{%0,%1,%2,%3}, {%4,%5,%6,%7}, {%8,%9}, {%0,%1,%2,%3};"
        : "+f"(c[0]), "+f"(c[1]), "+f"(c[2]), "+f"(c[3])
        : "r"(a[0]), "r"(a[1]), "r"(a[2]), "r"(a[3]), "r"(b[0]), "r"(b[1]));
}
// tf32 MMA m16n8k8 (single-pass GEMM path)
__device__ __forceinline__ void mma168tf(float* c, const uint32_t* a, const uint32_t* b) {
    asm volatile("mma.sync.aligned.m16n8k8.row.col.f32.tf32.tf32.f32 "
        "{%0,%1,%2,%3}, {%4,%5,%6,%7}, {%8,%9}, {%0,%1,%2,%3};"
        : "+f"(c[0]), "+f"(c[1]), "+f"(c[2]), "+f"(c[3])
        : "r"(a[0]), "r"(a[1]), "r"(a[2]), "r"(a[3]), "r"(b[0]), "r"(b[1]));
}
__device__ __forceinline__ void cpasync16(uint32_t s, const void* g) {
    asm volatile("cp.async.cg.shared.global [%0], [%1], 16;" :: "r"(s), "l"(g));
}
#define CP_COMMIT() asm volatile("cp.async.commit_group;" ::: "memory")
#define CP_WAIT(n)  asm volatile("cp.async.wait_group %0;" :: "n"(n) : "memory")

__device__ __forceinline__ uint32_t pack_bf16(float x, float y) {
    __nv_bfloat162 h = __float22bfloat162_rn(make_float2(x, y));
    return *(uint32_t*)&h;
}
__device__ __forceinline__ void split2(float x, float y, uint32_t& hi, uint32_t& lo) {
    __nv_bfloat162 h = __float22bfloat162_rn(make_float2(x, y));
    float2 hf = __bfloat1622float2(h);
    hi = *(uint32_t*)&h;
    lo = pack_bf16(x - hf.x, y - hf.y);
}
// round-to-nearest tf32 (store as fp32 bit pattern)
__device__ __forceinline__ float tf32r(float x) {
    uint32_t u;
    asm("cvt.rna.tf32.f32 %0, %1;" : "=r"(u) : "f"(x));
    return __uint_as_float(u);
}

// FFMA-pipe exp (valid for x <= 0)
__device__ __forceinline__ float fast_exp(float x) {
    const float L2E = 1.4426950408889634f;
    x = fmaxf(x, -80.0f);
    float t  = fmaf(x, L2E, 12582912.0f);
    int   n  = __float_as_int(t) - 0x4B400000;
    float f  = fmaf(x, L2E, -(t - 12582912.0f));
    float p  = 1.3333558e-3f;
    p = fmaf(p, f, 9.6181291e-3f);
    p = fmaf(p, f, 5.5504109e-2f);
    p = fmaf(p, f, 2.4022651e-1f);
    p = fmaf(p, f, 6.9314718e-1f);
    p = fmaf(p, f, 1.0f);
    return __int_as_float(__float_as_int(p) + (n << 23));
}

// Fixed softmax offset (RMS-normed q,k: |s| <= 11.32; see round 13)
#define FIXMAX 24.0f

// ---------------------------------------------------------------------------
// Scratch
// ---------------------------------------------------------------------------
#define SPLITK 2
#define KT_PER_SPLIT (Ln / 64 / SPLITK)

// split Q/K/V for attention (bf16 hi/lo; Q pre-scaled)
__device__ __align__(1024) __nv_bfloat16 g_qhi[(size_t)Bn * Hn  * Ln * Dn];
__device__ __align__(1024) __nv_bfloat16 g_qlo[(size_t)Bn * Hn  * Ln * Dn];
__device__ __align__(1024) __nv_bfloat16 g_khi[(size_t)Bn * KVn * Ln * Dn];
__device__ __align__(1024) __nv_bfloat16 g_klo[(size_t)Bn * KVn * Ln * Dn];
__device__ __align__(1024) __nv_bfloat16 g_vhi[(size_t)Bn * KVn * Ln * Dn];
__device__ __align__(1024) __nv_bfloat16 g_vlo[(size_t)Bn * KVn * Ln * Dn];

// split-K attention partials
__device__ __align__(1024) float g_Opart[(size_t)SPLITK * Bn * Ln * Hn * Dn];
__device__ __align__(1024) float g_lsum [(size_t)SPLITK * Bn * Hn * Ln];

// tf32-rounded fp32 operands for the GEMMs
__device__ __align__(1024) float g_Atf  [(size_t)Bn * Ln * HIDn];      // activations / attn out
__device__ __align__(1024) float g_WqTf [(size_t)Hn * Dn * HIDn];      // [N][K]
__device__ __align__(1024) float g_WkTf [(size_t)KVn * Dn * HIDn];
__device__ __align__(1024) float g_WvTf [(size_t)KVn * Dn * HIDn];
__device__ __align__(1024) float g_WoTf [(size_t)HIDn * Hn * Dn];

// ---------------------------------------------------------------------------
// Fused prep: tf32-round activations + transpose+round all 4 weights.
// ---------------------------------------------------------------------------
#define SPLIT_BLKS ((Bn * Ln * HIDn) / 1024)      // 8192
#define TRANS_BLKS (160 * (HIDn / 32))            // 10240

__global__ __launch_bounds__(256)
void prep_kernel(const float* __restrict__ hs,
                 const float* __restrict__ Wq, const float* __restrict__ Wk,
                 const float* __restrict__ Wv, const float* __restrict__ Wo)
{
    __shared__ float t[32][33];
    const int bid = blockIdx.x;

    if (bid < SPLIT_BLKS) {
        size_t i = ((size_t)bid * 256 + threadIdx.x) * 4;
        float4 v = *(const float4*)&hs[i];
        float4 r = make_float4(tf32r(v.x), tf32r(v.y), tf32r(v.z), tf32r(v.w));
        *(float4*)&g_Atf[i] = r;
        return;
    }

    const int tb = bid - SPLIT_BLKS;
    const int cb = tb % 160;
    const int ky = tb / 160;

    const float* src;
    float* dst;
    int N, c0;
    if (cb < 64)       { src = Wq; dst = g_WqTf; N = Hn * Dn;  c0 = cb; }
    else if (cb < 80)  { src = Wk; dst = g_WkTf; N = KVn * Dn; c0 = cb - 64; }
    else if (cb < 96)  { src = Wv; dst = g_WvTf; N = KVn * Dn; c0 = cb - 80; }
    else               { src = Wo; dst = g_WoTf; N = HIDn;     c0 = cb - 96; }

    const int tx = threadIdx.x & 31, ty = threadIdx.x >> 5;
#pragma unroll
    for (int j = 0; j < 4; j++) {
        int k = ky * 32 + ty + j * 8;
        t[ty + j * 8][tx] = src[(size_t)k * N + c0 * 32 + tx];
    }
    __syncthreads();
#pragma unroll
    for (int j = 0; j < 4; j++) {
        int n = c0 * 32 + ty + j * 8;
        int k = ky * 32 + tx;
        dst[(size_t)n * HIDn + k] = tf32r(t[tx][ty + j * 8]);
    }
}

// ---------------------------------------------------------------------------
// Single-pass tf32 GEMM, 128x128 tile per CTA.
// SMEM: double-buffered chunks of K=32 fp32: A tile + B tile, rows padded to
// 144 B (36 floats) — ldmatrix.b16 on 8x4-fp32 blocks yields the exact tf32
// fragment mapping (thread t <- element (t>>2, t&3)).
// ---------------------------------------------------------------------------
#define KC      32
#define NKCH    (HIDn / KC)        // 64
#define ROW4    144                // bytes per row (36 floats)
#define TILE4   (128 * ROW4)       // 18432
#define BUF4    (2 * TILE4)        // 36864
#define MM_SMEM (2 * BUF4)         // 73728
#define CSTR    132

template <bool QKV>
__global__ __launch_bounds__(256, 2)
void mm_kernel(const float* __restrict__ cosb, const float* __restrict__ sinb,
               const float* __restrict__ qw, const float* __restrict__ kw,
               float* __restrict__ outp)
{
    extern __shared__ char smc[];
    const uint32_t sb = smem_to_u32(smc);
    float* Cs = (float*)smc;

    const int tid = threadIdx.x;
    const int lane = tid & 31;
    const int wid = tid >> 5;
    const int warp_m = wid >> 2;
    const int warp_n = wid & 3;
    const int m0 = blockIdx.y * 128;
    const int n0 = blockIdx.x * 128;

    const float* Bw;
    int bcol = n0, sel = 0;
    if (QKV) {
        if (n0 < Hn * Dn)              { Bw = g_WqTf; sel = 0; bcol = n0; }
        else if (n0 < (Hn + KVn) * Dn) { Bw = g_WkTf; sel = 1; bcol = n0 - Hn * Dn; }
        else                           { Bw = g_WvTf; sel = 2; bcol = n0 - (Hn + KVn) * Dn; }
    } else {
        Bw = g_WoTf; bcol = n0;
    }

    float acc[4][4][4];
#pragma unroll
    for (int i = 0; i < 4; i++)
#pragma unroll
        for (int j = 0; j < 4; j++)
#pragma unroll
            for (int r = 0; r < 4; r++) acc[i][j][r] = 0.0f;

    auto load_chunk = [&](int ck, int buf) {
        const int kh = ck * KC;
#pragma unroll
        for (int it = 0; it < 8; it++) {
            const int idx = it * 256 + tid;      // 0..2047
            const int t   = idx >> 10;           // 0=A 1=B
            const int rem = idx & 1023;
            const int row = rem >> 3;
            const int seg = rem & 7;
            const uint32_t sa = sb + buf * BUF4 + t * TILE4 + row * ROW4 + seg * 16;
            const float* g = (t == 0) ? g_Atf + (size_t)(m0 + row) * HIDn
                                      : Bw    + (size_t)(bcol + row) * HIDn;
            cpasync16(sa, g + kh + seg * 4);
        }
    };

    // fragment base offsets (bytes) — see header comment for the mapping
    const uint32_t aoff = (uint32_t)(warp_m * 64 + (lane & 7) + ((lane >> 3) & 1) * 8) * ROW4
                        + (lane >> 4) * 16;
    const uint32_t boff = (uint32_t)(warp_n * 32 + (lane & 7) + ((lane >> 4) & 1) * 8) * ROW4
                        + ((lane >> 3) & 1) * 16;

    load_chunk(0, 0);
    CP_COMMIT();

    for (int ck = 0; ck < NKCH; ck++) {
        const int buf = ck & 1;
        if (ck + 1 < NKCH) {
            load_chunk(ck + 1, buf ^ 1);
            CP_COMMIT();
            CP_WAIT(1);
        } else {
            CP_WAIT(0);
        }
        __syncthreads();

        const uint32_t base = sb + buf * BUF4;
#pragma unroll
        for (int kk = 0; kk < 4; kk++) {
            uint32_t av[16], bv[8];
#pragma unroll
            for (int mt = 0; mt < 4; mt++)
                ldm_x4(&av[4 * mt], base + aoff + mt * (16 * ROW4) + kk * 32);
#pragma unroll
            for (int np = 0; np < 2; np++)
                ldm_x4(&bv[4 * np], base + TILE4 + boff + np * (16 * ROW4) + kk * 32);
#pragma unroll
            for (int mt = 0; mt < 4; mt++)
#pragma unroll
                for (int nt = 0; nt < 4; nt++)
                    mma168tf(acc[mt][nt], &av[4 * mt], &bv[2 * nt]);
        }
        __syncthreads();
    }

    // ---- epilogue: accum -> SMEM C tile ----
    {
        const int rb = warp_m * 64 + (lane >> 2);
        const int cb = warp_n * 32 + (lane & 3) * 2;
#pragma unroll
        for (int mt = 0; mt < 4; mt++)
#pragma unroll
            for (int nt = 0; nt < 4; nt++) {
                const int r = rb + mt * 16, c = cb + nt * 8;
                *(float2*)&Cs[r * CSTR + c]       = make_float2(acc[mt][nt][0], acc[mt][nt][1]);
                *(float2*)&Cs[(r + 8) * CSTR + c] = make_float2(acc[mt][nt][2], acc[mt][nt][3]);
            }
    }
    __syncthreads();

    if (QKV) {
        if (sel != 2 && tid < 128) {
            const float* nw = (sel == 0) ? qw : kw;
            float* row = Cs + tid * CSTR;
            float ss = 0.0f;
#pragma unroll 16
            for (int d = 0; d < 128; d++) ss += row[d] * row[d];
            const float rr = rsqrtf(ss * (1.0f / Dn) + 1e-6f);
            const int m = m0 + tid;
            const int b = m >> 11;
            const int l = m & (Ln - 1);
            const float* cp = cosb + ((size_t)b * Ln + l) * Dn;
            const float* sp = sinb + ((size_t)b * Ln + l) * Dn;
            const float post = (sel == 0) ? 0.08838834764831845f : 1.0f;
#pragma unroll 8
            for (int d = 0; d < 64; d++) {
                const float a  = row[d]      * rr * nw[d];
                const float b2 = row[d + 64] * rr * nw[d + 64];
                row[d]      = (a * cp[d]       - b2 * sp[d])     * post;
                row[d + 64] = (b2 * cp[d + 64] + a * sp[d + 64]) * post;
            }
        }
        __syncthreads();

        __nv_bfloat16 *dh, *dl;
        int NH, hh;
        if (sel == 0)      { dh = g_qhi; dl = g_qlo; NH = Hn;  hh = bcol >> 7; }
        else if (sel == 1) { dh = g_khi; dl = g_klo; NH = KVn; hh = bcol >> 7; }
        else               { dh = g_vhi; dl = g_vlo; NH = KVn; hh = bcol >> 7; }
#pragma unroll
        for (int it = 0; it < 16; it++) {
            const int idx = it * 256 + tid;
            const int row = idx >> 5;
            const int seg = idx & 31;
            const float4 v = *(float4*)&Cs[row * CSTR + seg * 4];
            const int m = m0 + row;
            const int b = m >> 11;
            const int l = m & (Ln - 1);
            const size_t off = (((size_t)b * NH + hh) * Ln + l) * Dn + seg * 4;
            uint32_t h01, l01, h23, l23;
            split2(v.x, v.y, h01, l01);
            split2(v.z, v.w, h23, l23);
            uint2 hv = {h01, h23}, lv = {l01, l23};
            *(uint2*)&dh[off] = hv;
            *(uint2*)&dl[off] = lv;
        }
    } else {
#pragma unroll
        for (int it = 0; it < 16; it++) {
            const int idx = it * 256 + tid;
            const int row = idx >> 5;
            const int seg = idx & 31;
            const float4 v = *(float4*)&Cs[row * CSTR + seg * 4];
            *(float4*)&outp[(size_t)(m0 + row) * HIDn + n0 + seg * 4] = v;
        }
    }
}

// ---------------------------------------------------------------------------
// Tensor-core flash attention, split-K=2, fixed-max softmax (round-13 proven).
// ---------------------------------------------------------------------------
#define ASTR_B   272
#define QSUB_B   (128 * ASTR_B)
#define KSUB_B   (64 * ASTR_B)
#define KV_OFF   (2 * QSUB_B)
#define KVBUF_B  (4 * KSUB_B)
#define ATTN_SMEM (KV_OFF + 2 * KVBUF_B)  // 208896

__global__ __launch_bounds__(256, 1)
void attn_kernel()
{
    extern __shared__ char sm[];
    const uint32_t sb = smem_to_u32(sm);
    const int tid = threadIdx.x, lane = tid & 31, wid = tid >> 5;
    const int qt = blockIdx.x, h = blockIdx.y;
    const int b  = blockIdx.z >> 1, kz = blockIdx.z & 1;
    const int g  = h >> 2;

    const __nv_bfloat16* Qh = g_qhi + (((size_t)b * Hn + h) * Ln + qt * 128) * Dn;
    const __nv_bfloat16* Ql = g_qlo + (((size_t)b * Hn + h) * Ln + qt * 128) * Dn;
    const __nv_bfloat16* Kh = g_khi + ((size_t)b * KVn + g) * Ln * Dn;
    const __nv_bfloat16* Kl = g_klo + ((size_t)b * KVn + g) * Ln * Dn;
    const __nv_bfloat16* Vh = g_vhi + ((size_t)b * KVn + g) * Ln * Dn;
    const __nv_bfloat16* Vl = g_vlo + ((size_t)b * KVn + g) * Ln * Dn;

#pragma unroll
    for (int it = 0; it < 16; it++) {
        const int sub = it >> 3;
        const int r   = (it & 7) * 16 + (tid >> 4);
        const int c   = tid & 15;
        const __nv_bfloat16* src = (sub == 0) ? Qh : Ql;
        cpasync16(sb + sub * QSUB_B + r * ASTR_B + c * 16, src + (size_t)r * Dn + c * 8);
    }

    auto load_kv = [&](int kt, int buf) {
#pragma unroll
        for (int it = 0; it < 16; it++) {
            const int sub = it >> 2;
            const int r   = (it & 3) * 16 + (tid >> 4);
            const int c   = tid & 15;
            const __nv_bfloat16* src;
            if (sub == 0)      src = Kh;
            else if (sub == 1) src = Kl;
            else if (sub == 2) src = Vh;
            else               src = Vl;
            cpasync16(sb + KV_OFF + buf * KVBUF_B + sub * KSUB_B + r * ASTR_B + c * 16,
                      src + (size_t)(kt * 64 + r) * Dn + c * 8);
        }
    };

    const int KT0 = kz * KT_PER_SPLIT;
    const int KT1 = KT0 + KT_PER_SPLIT;
    load_kv(KT0, 0);
    CP_COMMIT();

    float o[16][4];
#pragma unroll
    for (int i = 0; i < 16; i++)
#pragma unroll
        for (int j = 0; j < 4; j++) o[i][j] = 0.0f;
    float lsum0 = 0.0f, lsum1 = 0.0f;

    const uint32_t aoffQ = (uint32_t)(wid * 16 + (lane & 15)) * ASTR_B + ((lane >> 4) << 4);
    const uint32_t boffK = (uint32_t)((lane & 7) + ((lane >> 4) << 3)) * ASTR_B
                         + (((lane >> 3) & 1) << 4);
    const uint32_t voffR = (uint32_t)((lane & 7) + (((lane >> 3) & 1) << 3)) * ASTR_B
                         + ((lane >> 4) << 4);

    for (int kt = KT0; kt < KT1; kt++) {
        const int buf = kt & 1;
        if (kt + 1 < KT1) {
            load_kv(kt + 1, buf ^ 1);
            CP_COMMIT();
            CP_WAIT(1);
        } else {
            CP_WAIT(0);
        }
        __syncthreads();

        const uint32_t kb = sb + KV_OFF + buf * KVBUF_B;

        float s[8][4];
#pragma unroll
        for (int i = 0; i < 8; i++)
#pragma unroll
            for (int j = 0; j < 4; j++) s[i][j] = 0.0f;

#pragma unroll
        for (int kk = 0; kk < 8; kk++) {
            uint32_t aH[4], aL[4], bb[16];
            ldm_x4(aH, sb + aoffQ + kk * 32);
            ldm_x4(aL, sb + QSUB_B + aoffQ + kk * 32);
#pragma unroll
            for (int p = 0; p < 4; p++)
                ldm_x4(&bb[4 * p], kb + boffK + p * (16 * ASTR_B) + kk * 32);
#pragma unroll
            for (int nt = 0; nt < 8; nt++) mma16816(s[nt], aH, &bb[2 * nt]);
#pragma unroll
            for (int nt = 0; nt < 8; nt++) mma16816(s[nt], aL, &bb[2 * nt]);
#pragma unroll
            for (int p = 0; p < 4; p++)
                ldm_x4(&bb[4 * p], kb + KSUB_B + boffK + p * (16 * ASTR_B) + kk * 32);
#pragma unroll
            for (int nt = 0; nt < 8; nt++) mma16816(s[nt], aH, &bb[2 * nt]);
        }

        // fixed-max softmax
#pragma unroll
        for (int nt = 0; nt < 8; nt++) {
            s[nt][0] = fast_exp(s[nt][0] - FIXMAX);
            s[nt][1] = fast_exp(s[nt][1] - FIXMAX);
            s[nt][2] = fast_exp(s[nt][2] - FIXMAX);
            s[nt][3] = fast_exp(s[nt][3] - FIXMAX);
            lsum0 += s[nt][0] + s[nt][1];
            lsum1 += s[nt][2] + s[nt][3];
        }

        // O += Phi*Vhi + Plo*Vhi + Phi*Vlo
#pragma unroll
        for (int kk = 0; kk < 4; kk++) {
            uint32_t pH[4], pL[4];
            split2(s[2 * kk][0],     s[2 * kk][1],     pH[0], pL[0]);
            split2(s[2 * kk][2],     s[2 * kk][3],     pH[1], pL[1]);
            split2(s[2 * kk + 1][0], s[2 * kk + 1][1], pH[2], pL[2]);
            split2(s[2 * kk + 1][2], s[2 * kk + 1][3], pH[3], pL[3]);

            uint32_t vv[32];
            const uint32_t vrow = kk * (16 * ASTR_B) + voffR;
#pragma unroll
            for (int p = 0; p < 8; p++)
                ldm_x4t(&vv[4 * p], kb + 2 * KSUB_B + vrow + p * 32);
#pragma unroll
            for (int nt = 0; nt < 16; nt++) mma16816(o[nt], pH, &vv[2 * nt]);
#pragma unroll
            for (int nt = 0; nt < 16; nt++) mma16816(o[nt], pL, &vv[2 * nt]);
#pragma unroll
            for (int p = 0; p < 8; p++)
                ldm_x4t(&vv[4 * p], kb + 3 * KSUB_B + vrow + p * 32);
#pragma unroll
            for (int nt = 0; nt < 16; nt++) mma16816(o[nt], pH, &vv[2 * nt]);
        }
        __syncthreads();
    }

    lsum0 += __shfl_xor_sync(0xffffffffu, lsum0, 1);
    lsum0 += __shfl_xor_sync(0xffffffffu, lsum0, 2);
    lsum1 += __shfl_xor_sync(0xffffffffu, lsum1, 1);
    lsum1 += __shfl_xor_sync(0xffffffffu, lsum1, 2);

    const int q0 = qt * 128 + wid * 16 + (lane >> 2);
    if ((lane & 3) == 0) {
        g_lsum[(((size_t)kz * Bn + b) * Hn + h) * Ln + q0]     = lsum0;
        g_lsum[(((size_t)kz * Bn + b) * Hn + h) * Ln + q0 + 8] = lsum1;
    }
    const size_t r0 = (((size_t)kz * Bn + b) * Ln + q0) * (Hn * Dn) + h * Dn;
    const size_t r1 = r0 + (size_t)8 * Hn * Dn;
#pragma unroll
    for (int nt = 0; nt < 16; nt++) {
        const int d = nt * 8 + (lane & 3) * 2;
        *(float2*)&g_Opart[r0 + d] = make_float2(o[nt][0], o[nt][1]);
        *(float2*)&g_Opart[r1 + d] = make_float2(o[nt][2], o[nt][3]);
    }
}

// ---------------------------------------------------------------------------
// Merge: partials add (shared fixed max); normalize; emit tf32-rounded fp32
// into g_Atf (the Wo GEMM's A operand).
// ---------------------------------------------------------------------------
__global__ __launch_bounds__(256)
void merge_kernel()
{
    const size_t gid = (size_t)blockIdx.x * 256 + threadIdx.x;
    const size_t e4 = gid * 4;
    const size_t row = e4 >> 7;
    const int hh = (int)(row & (Hn - 1));
    const size_t bl = row >> 4;
    const int l = (int)(bl & (Ln - 1));
    const int b = (int)(bl >> 11);

    const float l0 = g_lsum[(((size_t)0 * Bn + b) * Hn + hh) * Ln + l];
    const float l1 = g_lsum[(((size_t)1 * Bn + b) * Hn + hh) * Ln + l];
    const float inv = 1.0f / (l0 + l1);

    const float4 vA = *(const float4*)&g_Opart[e4];
    const float4 vB = *(const float4*)&g_Opart[(size_t)Bn * Ln * Hn * Dn + e4];
    float4 r;
    r.x = tf32r((vA.x + vB.x) * inv);
    r.y = tf32r((vA.y + vB.y) * inv);
    r.z = tf32r((vA.z + vB.z) * inv);
    r.w = tf32r((vA.w + vB.w) * inv);
    *(float4*)&g_Atf[e4] = r;
}

// ---------------------------------------------------------------------------
extern "C" void kernel_launch(void* const* d_in, const int* in_sizes, int n_in,
                              void* d_out, int out_size)
{
    const float* hs = (const float*)d_in[0];
    const float* cs = (const float*)d_in[1];
    const float* sn = (const float*)d_in[2];
    const float* Wq = (const float*)d_in[3];
    const float* Wk = (const float*)d_in[4];
    const float* Wv = (const float*)d_in[5];
    const float* Wo = (const float*)d_in[6];
    const float* qw = (const float*)d_in[7];
    const float* kw = (const float*)d_in[8];
    float* out = (float*)d_out;

    cudaFuncSetAttribute(mm_kernel<true>,  cudaFuncAttributeMaxDynamicSharedMemorySize, MM_SMEM);
    cudaFuncSetAttribute(mm_kernel<false>, cudaFuncAttributeMaxDynamicSharedMemorySize, MM_SMEM);
    cudaFuncSetAttribute(attn_kernel, cudaFuncAttributeMaxDynamicSharedMemorySize, ATTN_SMEM);

    // Fused prep (tf32 rounding + weight transpose)
    prep_kernel<<<SPLIT_BLKS + TRANS_BLKS, 256>>>(hs, Wq, Wk, Wv, Wo);

    // Fused QKV projection (single-pass tf32)
    mm_kernel<true><<<dim3((Hn + 2 * KVn) * Dn / 128, (Bn * Ln) / 128), 256, MM_SMEM>>>(
        cs, sn, qw, kw, nullptr);

    // Split-K flash attention (split-bf16, fixed-max) + merge
    attn_kernel<<<dim3(Ln / 128, Hn, Bn * SPLITK), 256, ATTN_SMEM>>>();
    merge_kernel<<<(Bn * Ln * Hn * Dn) / 1024, 256>>>();

    // Output projection (single-pass tf32)
    mm_kernel<false><<<dim3(HIDn / 128, (Bn * Ln) / 128), 256, MM_SMEM>>>(
        nullptr, nullptr, nullptr, nullptr, out);
}

// round 15
// speedup vs baseline: 1.2683x; 1.0114x over previous
#include <cuda_runtime.h>
#include <cuda_bf16.h>
#include <math.h>
#include <stdint.h>

// Problem constants
#define Bn   2
#define Ln   2048
#define Hn   16
#define KVn  4
#define Dn   128
#define HIDn 2048

// ---------------------------------------------------------------------------
// Portable tensor-core helpers (sm_80+ PTX only)
// ---------------------------------------------------------------------------
__device__ __forceinline__ uint32_t smem_to_u32(const void* p) {
    uint32_t a;
    asm("{ .reg .u64 t; cvta.to.shared.u64 t, %1; cvt.u32.u64 %0, t; }" : "=r"(a) : "l"(p));
    return a;
}
__device__ __forceinline__ void ldm_x4(uint32_t* r, uint32_t a) {
    asm volatile("ldmatrix.sync.aligned.m8n8.x4.shared.b16 {%0,%1,%2,%3}, [%4];"
        : "=r"(r[0]), "=r"(r[1]), "=r"(r[2]), "=r"(r[3]) : "r"(a));
}
__device__ __forceinline__ void ldm_x4t(uint32_t* r, uint32_t a) {
    asm volatile("ldmatrix.sync.aligned.m8n8.x4.trans.shared.b16 {%0,%1,%2,%3}, [%4];"
        : "=r"(r[0]), "=r"(r[1]), "=r"(r[2]), "=r"(r[3]) : "r"(a));
}
__device__ __forceinline__ void mma16816(float* c, const uint32_t* a, const uint32_t* b) {
    asm volatile("mma.sync.aligned.m16n8k16.row.col.f32.bf16.bf16.f32 "
        "{%0,%1,%2,%3}, {%4,%5,%6,%7}, {%8,%9}, {%0,%1,%2,%3};"
        : "+f"(c[0]), "+f"(c[1]), "+f"(c[2]), "+f"(c[3])
        : "r"(a[0]), "r"(a[1]), "r"(a[2]), "r"(a[3]), "r"(b[0]), "r"(b[1]));
}
// tf32 MMA m16n8k8 (single-pass GEMM path)
__device__ __forceinline__ void mma168tf(float* c, const uint32_t* a, const uint32_t* b) {
    asm volatile("mma.sync.aligned.m16n8k8.row.col.f32.tf32.tf32.f32 "
        "{%0,%1,%2,%3}, {%4,%5,%6,%7}, {%8,%9}, {%0,%1,%2,%3};"
        : "+f"(c[0]), "+f"(c[1]), "+f"(c[2]), "+f"(c[3])
        : "r"(a[0]), "r"(a[1]), "r"(a[2]), "r"(a[3]), "r"(b[0]), "r"(b[1]));
}
__device__ __forceinline__ void cpasync16(uint32_t s, const void* g) {
    asm volatile("cp.async.cg.shared.global [%0], [%1], 16;" :: "r"(s), "l"(g));
}
#define CP_COMMIT() asm volatile("cp.async.commit_group;" ::: "memory")
#define CP_WAIT(n)  asm volatile("cp.async.wait_group %0;" :: "n"(n) : "memory")

__device__ __forceinline__ uint32_t pack_bf16(float x, float y) {
    __nv_bfloat162 h = __float22bfloat162_rn(make_float2(x, y));
    return *(uint32_t*)&h;
}
__device__ __forceinline__ void split2(float x, float y, uint32_t& hi, uint32_t& lo) {
    __nv_bfloat162 h = __float22bfloat162_rn(make_float2(x, y));
    float2 hf = __bfloat1622float2(h);
    hi = *(uint32_t*)&h;
    lo = pack_bf16(x - hf.x, y - hf.y);
}
// round-to-nearest tf32 (store as fp32 bit pattern)
__device__ __forceinline__ float tf32r(float x) {
    uint32_t u;
    asm("cvt.rna.tf32.f32 %0, %1;" : "=r"(u) : "f"(x));
    return __uint_as_float(u);
}

// FFMA-pipe exp (valid for x <= 0)
__device__ __forceinline__ float fast_exp(float x) {
    const float L2E = 1.4426950408889634f;
    x = fmaxf(x, -80.0f);
    float t  = fmaf(x, L2E, 12582912.0f);
    int   n  = __float_as_int(t) - 0x4B400000;
    float f  = fmaf(x, L2E, -(t - 12582912.0f));
    float p  = 1.3333558e-3f;
    p = fmaf(p, f, 9.6181291e-3f);
    p = fmaf(p, f, 5.5504109e-2f);
    p = fmaf(p, f, 2.4022651e-1f);
    p = fmaf(p, f, 6.9314718e-1f);
    p = fmaf(p, f, 1.0f);
    return __int_as_float(__float_as_int(p) + (n << 23));
}

// Fixed softmax offset (RMS-normed q,k: |s| <= 11.32; see round 13)
#define FIXMAX 24.0f

// ---------------------------------------------------------------------------
// Scratch
// ---------------------------------------------------------------------------
#define SPLITK 2
#define KT_PER_SPLIT (Ln / 64 / SPLITK)

__device__ __align__(1024) __nv_bfloat16 g_qhi[(size_t)Bn * Hn  * Ln * Dn];
__device__ __align__(1024) __nv_bfloat16 g_qlo[(size_t)Bn * Hn  * Ln * Dn];
__device__ __align__(1024) __nv_bfloat16 g_khi[(size_t)Bn * KVn * Ln * Dn];
__device__ __align__(1024) __nv_bfloat16 g_klo[(size_t)Bn * KVn * Ln * Dn];
__device__ __align__(1024) __nv_bfloat16 g_vhi[(size_t)Bn * KVn * Ln * Dn];
__device__ __align__(1024) __nv_bfloat16 g_vlo[(size_t)Bn * KVn * Ln * Dn];

__device__ __align__(1024) float g_Opart[(size_t)SPLITK * Bn * Ln * Hn * Dn];
__device__ __align__(1024) float g_lsum [(size_t)SPLITK * Bn * Hn * Ln];

__device__ __align__(1024) float g_Atf  [(size_t)Bn * Ln * HIDn];
__device__ __align__(1024) float g_WqTf [(size_t)Hn * Dn * HIDn];
__device__ __align__(1024) float g_WkTf [(size_t)KVn * Dn * HIDn];
__device__ __align__(1024) float g_WvTf [(size_t)KVn * Dn * HIDn];
__device__ __align__(1024) float g_WoTf [(size_t)HIDn * Hn * Dn];

// ---------------------------------------------------------------------------
// Fused prep: tf32-round activations + transpose+round all 4 weights.
// ---------------------------------------------------------------------------
#define SPLIT_BLKS ((Bn * Ln * HIDn) / 1024)      // 8192
#define TRANS_BLKS (160 * (HIDn / 32))            // 10240

__global__ __launch_bounds__(256)
void prep_kernel(const float* __restrict__ hs,
                 const float* __restrict__ Wq, const float* __restrict__ Wk,
                 const float* __restrict__ Wv, const float* __restrict__ Wo)
{
    __shared__ float t[32][33];
    const int bid = blockIdx.x;

    if (bid < SPLIT_BLKS) {
        size_t i = ((size_t)bid * 256 + threadIdx.x) * 4;
        float4 v = *(const float4*)&hs[i];
        float4 r = make_float4(tf32r(v.x), tf32r(v.y), tf32r(v.z), tf32r(v.w));
        *(float4*)&g_Atf[i] = r;
        return;
    }

    const int tb = bid - SPLIT_BLKS;
    const int cb = tb % 160;
    const int ky = tb / 160;

    const float* src;
    float* dst;
    int N, c0;
    if (cb < 64)       { src = Wq; dst = g_WqTf; N = Hn * Dn;  c0 = cb; }
    else if (cb < 80)  { src = Wk; dst = g_WkTf; N = KVn * Dn; c0 = cb - 64; }
    else if (cb < 96)  { src = Wv; dst = g_WvTf; N = KVn * Dn; c0 = cb - 80; }
    else               { src = Wo; dst = g_WoTf; N = HIDn;     c0 = cb - 96; }

    const int tx = threadIdx.x & 31, ty = threadIdx.x >> 5;
#pragma unroll
    for (int j = 0; j < 4; j++) {
        int k = ky * 32 + ty + j * 8;
        t[ty + j * 8][tx] = src[(size_t)k * N + c0 * 32 + tx];
    }
    __syncthreads();
#pragma unroll
    for (int j = 0; j < 4; j++) {
        int n = c0 * 32 + ty + j * 8;
        int k = ky * 32 + tx;
        dst[(size_t)n * HIDn + k] = tf32r(t[tx][ty + j * 8]);
    }
}

// ---------------------------------------------------------------------------
// Single-pass tf32 GEMM, 128x128 tile per CTA (unchanged from round 14).
// ---------------------------------------------------------------------------
#define KC      32
#define NKCH    (HIDn / KC)        // 64
#define ROW4    144                // bytes per row (36 floats)
#define TILE4   (128 * ROW4)       // 18432
#define BUF4    (2 * TILE4)        // 36864
#define MM_SMEM (2 * BUF4)         // 73728
#define CSTR    132

template <bool QKV>
__global__ __launch_bounds__(256, 2)
void mm_kernel(const float* __restrict__ cosb, const float* __restrict__ sinb,
               const float* __restrict__ qw, const float* __restrict__ kw,
               float* __restrict__ outp)
{
    extern __shared__ char smc[];
    const uint32_t sb = smem_to_u32(smc);
    float* Cs = (float*)smc;

    const int tid = threadIdx.x;
    const int lane = tid & 31;
    const int wid = tid >> 5;
    const int warp_m = wid >> 2;
    const int warp_n = wid & 3;
    const int m0 = blockIdx.y * 128;
    const int n0 = blockIdx.x * 128;

    const float* Bw;
    int bcol = n0, sel = 0;
    if (QKV) {
        if (n0 < Hn * Dn)              { Bw = g_WqTf; sel = 0; bcol = n0; }
        else if (n0 < (Hn + KVn) * Dn) { Bw = g_WkTf; sel = 1; bcol = n0 - Hn * Dn; }
        else                           { Bw = g_WvTf; sel = 2; bcol = n0 - (Hn + KVn) * Dn; }
    } else {
        Bw = g_WoTf; bcol = n0;
    }

    float acc[4][4][4];
#pragma unroll
    for (int i = 0; i < 4; i++)
#pragma unroll
        for (int j = 0; j < 4; j++)
#pragma unroll
            for (int r = 0; r < 4; r++) acc[i][j][r] = 0.0f;

    auto load_chunk = [&](int ck, int buf) {
        const int kh = ck * KC;
#pragma unroll
        for (int it = 0; it < 8; it++) {
            const int idx = it * 256 + tid;
            const int t   = idx >> 10;
            const int rem = idx & 1023;
            const int row = rem >> 3;
            const int seg = rem & 7;
            const uint32_t sa = sb + buf * BUF4 + t * TILE4 + row * ROW4 + seg * 16;
            const float* g = (t == 0) ? g_Atf + (size_t)(m0 + row) * HIDn
                                      : Bw    + (size_t)(bcol + row) * HIDn;
            cpasync16(sa, g + kh + seg * 4);
        }
    };

    const uint32_t aoff = (uint32_t)(warp_m * 64 + (lane & 7) + ((lane >> 3) & 1) * 8) * ROW4
                        + (lane >> 4) * 16;
    const uint32_t boff = (uint32_t)(warp_n * 32 + (lane & 7) + ((lane >> 4) & 1) * 8) * ROW4
                        + ((lane >> 3) & 1) * 16;

    load_chunk(0, 0);
    CP_COMMIT();

    for (int ck = 0; ck < NKCH; ck++) {
        const int buf = ck & 1;
        if (ck + 1 < NKCH) {
            load_chunk(ck + 1, buf ^ 1);
            CP_COMMIT();
            CP_WAIT(1);
        } else {
            CP_WAIT(0);
        }
        __syncthreads();

        const uint32_t base = sb + buf * BUF4;
#pragma unroll
        for (int kk = 0; kk < 4; kk++) {
            uint32_t av[16], bv[8];
#pragma unroll
            for (int mt = 0; mt < 4; mt++)
                ldm_x4(&av[4 * mt], base + aoff + mt * (16 * ROW4) + kk * 32);
#pragma unroll
            for (int np = 0; np < 2; np++)
                ldm_x4(&bv[4 * np], base + TILE4 + boff + np * (16 * ROW4) + kk * 32);
#pragma unroll
            for (int mt = 0; mt < 4; mt++)
#pragma unroll
                for (int nt = 0; nt < 4; nt++)
                    mma168tf(acc[mt][nt], &av[4 * mt], &bv[2 * nt]);
        }
        __syncthreads();
    }

    {
        const int rb = warp_m * 64 + (lane >> 2);
        const int cb = warp_n * 32 + (lane & 3) * 2;
#pragma unroll
        for (int mt = 0; mt < 4; mt++)
#pragma unroll
            for (int nt = 0; nt < 4; nt++) {
                const int r = rb + mt * 16, c = cb + nt * 8;
                *(float2*)&Cs[r * CSTR + c]       = make_float2(acc[mt][nt][0], acc[mt][nt][1]);
                *(float2*)&Cs[(r + 8) * CSTR + c] = make_float2(acc[mt][nt][2], acc[mt][nt][3]);
            }
    }
    __syncthreads();

    if (QKV) {
        if (sel != 2 && tid < 128) {
            const float* nw = (sel == 0) ? qw : kw;
            float* row = Cs + tid * CSTR;
            float ss = 0.0f;
#pragma unroll 16
            for (int d = 0; d < 128; d++) ss += row[d] * row[d];
            const float rr = rsqrtf(ss * (1.0f / Dn) + 1e-6f);
            const int m = m0 + tid;
            const int b = m >> 11;
            const int l = m & (Ln - 1);
            const float* cp = cosb + ((size_t)b * Ln + l) * Dn;
            const float* sp = sinb + ((size_t)b * Ln + l) * Dn;
            const float post = (sel == 0) ? 0.08838834764831845f : 1.0f;
#pragma unroll 8
            for (int d = 0; d < 64; d++) {
                const float a  = row[d]      * rr * nw[d];
                const float b2 = row[d + 64] * rr * nw[d + 64];
                row[d]      = (a * cp[d]       - b2 * sp[d])     * post;
                row[d + 64] = (b2 * cp[d + 64] + a * sp[d + 64]) * post;
            }
        }
        __syncthreads();

        __nv_bfloat16 *dh, *dl;
        int NH, hh;
        if (sel == 0)      { dh = g_qhi; dl = g_qlo; NH = Hn;  hh = bcol >> 7; }
        else if (sel == 1) { dh = g_khi; dl = g_klo; NH = KVn; hh = bcol >> 7; }
        else               { dh = g_vhi; dl = g_vlo; NH = KVn; hh = bcol >> 7; }
#pragma unroll
        for (int it = 0; it < 16; it++) {
            const int idx = it * 256 + tid;
            const int row = idx >> 5;
            const int seg = idx & 31;
            const float4 v = *(float4*)&Cs[row * CSTR + seg * 4];
            const int m = m0 + row;
            const int b = m >> 11;
            const int l = m & (Ln - 1);
            const size_t off = (((size_t)b * NH + hh) * Ln + l) * Dn + seg * 4;
            uint32_t h01, l01, h23, l23;
            split2(v.x, v.y, h01, l01);
            split2(v.z, v.w, h23, l23);
            uint2 hv = {h01, h23}, lv = {l01, l23};
            *(uint2*)&dh[off] = hv;
            *(uint2*)&dl[off] = lv;
        }
    } else {
#pragma unroll
        for (int it = 0; it < 16; it++) {
            const int idx = it * 256 + tid;
            const int row = idx >> 5;
            const int seg = idx & 31;
            const float4 v = *(float4*)&Cs[row * CSTR + seg * 4];
            *(float4*)&outp[(size_t)(m0 + row) * HIDn + n0 + seg * 4] = v;
        }
    }
}

// ---------------------------------------------------------------------------
// Tensor-core flash attention, split-K=2, fixed-max softmax.
// NEW: Q fragments hoisted to registers once (invariant across key tiles) —
// removes 512 LDSM per CTA and the Q dependency at each tile's S phase.
// ---------------------------------------------------------------------------
#define ASTR_B   272
#define QSUB_B   (128 * ASTR_B)
#define KSUB_B   (64 * ASTR_B)
#define KV_OFF   (2 * QSUB_B)
#define KVBUF_B  (4 * KSUB_B)
#define ATTN_SMEM (KV_OFF + 2 * KVBUF_B)  // 208896

__global__ __launch_bounds__(256, 1)
void attn_kernel()
{
    extern __shared__ char sm[];
    const uint32_t sb = smem_to_u32(sm);
    const int tid = threadIdx.x, lane = tid & 31, wid = tid >> 5;
    const int qt = blockIdx.x, h = blockIdx.y;
    const int b  = blockIdx.z >> 1, kz = blockIdx.z & 1;
    const int g  = h >> 2;

    const __nv_bfloat16* Qh = g_qhi + (((size_t)b * Hn + h) * Ln + qt * 128) * Dn;
    const __nv_bfloat16* Ql = g_qlo + (((size_t)b * Hn + h) * Ln + qt * 128) * Dn;
    const __nv_bfloat16* Kh = g_khi + ((size_t)b * KVn + g) * Ln * Dn;
    const __nv_bfloat16* Kl = g_klo + ((size_t)b * KVn + g) * Ln * Dn;
    const __nv_bfloat16* Vh = g_vhi + ((size_t)b * KVn + g) * Ln * Dn;
    const __nv_bfloat16* Vl = g_vlo + ((size_t)b * KVn + g) * Ln * Dn;

    // Q hi/lo -> smem (own cp.async group)
#pragma unroll
    for (int it = 0; it < 16; it++) {
        const int sub = it >> 3;
        const int r   = (it & 7) * 16 + (tid >> 4);
        const int c   = tid & 15;
        const __nv_bfloat16* src = (sub == 0) ? Qh : Ql;
        cpasync16(sb + sub * QSUB_B + r * ASTR_B + c * 16, src + (size_t)r * Dn + c * 8);
    }
    CP_COMMIT();

    auto load_kv = [&](int kt, int buf) {
#pragma unroll
        for (int it = 0; it < 16; it++) {
            const int sub = it >> 2;
            const int r   = (it & 3) * 16 + (tid >> 4);
            const int c   = tid & 15;
            const __nv_bfloat16* src;
            if (sub == 0)      src = Kh;
            else if (sub == 1) src = Kl;
            else if (sub == 2) src = Vh;
            else               src = Vl;
            cpasync16(sb + KV_OFF + buf * KVBUF_B + sub * KSUB_B + r * ASTR_B + c * 16,
                      src + (size_t)(kt * 64 + r) * Dn + c * 8);
        }
    };

    const int KT0 = kz * KT_PER_SPLIT;
    const int KT1 = KT0 + KT_PER_SPLIT;
    load_kv(KT0, 0);
    CP_COMMIT();

    const uint32_t aoffQ = (uint32_t)(wid * 16 + (lane & 15)) * ASTR_B + ((lane >> 4) << 4);
    const uint32_t boffK = (uint32_t)((lane & 7) + ((lane >> 4) << 3)) * ASTR_B
                         + (((lane >> 3) & 1) << 4);
    const uint32_t voffR = (uint32_t)((lane & 7) + (((lane >> 3) & 1) << 3)) * ASTR_B
                         + ((lane >> 4) << 4);

    // wait for the Q group (KV0 may still be in flight), then hoist fragments
    CP_WAIT(1);
    __syncthreads();
    uint32_t aHq[32], aLq[32];
#pragma unroll
    for (int kk = 0; kk < 8; kk++) {
        ldm_x4(&aHq[4 * kk], sb + aoffQ + kk * 32);
        ldm_x4(&aLq[4 * kk], sb + QSUB_B + aoffQ + kk * 32);
    }

    float o[16][4];
#pragma unroll
    for (int i = 0; i < 16; i++)
#pragma unroll
        for (int j = 0; j < 4; j++) o[i][j] = 0.0f;
    float lsum0 = 0.0f, lsum1 = 0.0f;

    for (int kt = KT0; kt < KT1; kt++) {
        const int buf = kt & 1;
        if (kt + 1 < KT1) {
            load_kv(kt + 1, buf ^ 1);
            CP_COMMIT();
            CP_WAIT(1);
        } else {
            CP_WAIT(0);
        }
        __syncthreads();

        const uint32_t kb = sb + KV_OFF + buf * KVBUF_B;

        float s[8][4];
#pragma unroll
        for (int i = 0; i < 8; i++)
#pragma unroll
            for (int j = 0; j < 4; j++) s[i][j] = 0.0f;

#pragma unroll
        for (int kk = 0; kk < 8; kk++) {
            uint32_t bb[16];
#pragma unroll
            for (int p = 0; p < 4; p++)
                ldm_x4(&bb[4 * p], kb + boffK + p * (16 * ASTR_B) + kk * 32);
#pragma unroll
            for (int nt = 0; nt < 8; nt++) mma16816(s[nt], &aHq[4 * kk], &bb[2 * nt]);
#pragma unroll
            for (int nt = 0; nt < 8; nt++) mma16816(s[nt], &aLq[4 * kk], &bb[2 * nt]);
#pragma unroll
            for (int p = 0; p < 4; p++)
                ldm_x4(&bb[4 * p], kb + KSUB_B + boffK + p * (16 * ASTR_B) + kk * 32);
#pragma unroll
            for (int nt = 0; nt < 8; nt++) mma16816(s[nt], &aHq[4 * kk], &bb[2 * nt]);
        }

        // fixed-max softmax
#pragma unroll
        for (int nt = 0; nt < 8; nt++) {
            s[nt][0] = fast_exp(s[nt][0] - FIXMAX);
            s[nt][1] = fast_exp(s[nt][1] - FIXMAX);
            s[nt][2] = fast_exp(s[nt][2] - FIXMAX);
            s[nt][3] = fast_exp(s[nt][3] - FIXMAX);
            lsum0 += s[nt][0] + s[nt][1];
            lsum1 += s[nt][2] + s[nt][3];
        }

        // O += Phi*Vhi + Plo*Vhi + Phi*Vlo
#pragma unroll
        for (int kk = 0; kk < 4; kk++) {
            uint32_t pH[4], pL[4];
            split2(s[2 * kk][0],     s[2 * kk][1],     pH[0], pL[0]);
            split2(s[2 * kk][2],     s[2 * kk][3],     pH[1], pL[1]);
            split2(s[2 * kk + 1][0], s[2 * kk + 1][1], pH[2], pL[2]);
            split2(s[2 * kk + 1][2], s[2 * kk + 1][3], pH[3], pL[3]);

            uint32_t vv[32];
            const uint32_t vrow = kk * (16 * ASTR_B) + voffR;
#pragma unroll
            for (int p = 0; p < 8; p++)
                ldm_x4t(&vv[4 * p], kb + 2 * KSUB_B + vrow + p * 32);
#pragma unroll
            for (int nt = 0; nt < 16; nt++) mma16816(o[nt], pH, &vv[2 * nt]);
#pragma unroll
            for (int nt = 0; nt < 16; nt++) mma16816(o[nt], pL, &vv[2 * nt]);
#pragma unroll
            for (int p = 0; p < 8; p++)
                ldm_x4t(&vv[4 * p], kb + 3 * KSUB_B + vrow + p * 32);
#pragma unroll
            for (int nt = 0; nt < 16; nt++) mma16816(o[nt], pH, &vv[2 * nt]);
        }
        __syncthreads();
    }

    lsum0 += __shfl_xor_sync(0xffffffffu, lsum0, 1);
    lsum0 += __shfl_xor_sync(0xffffffffu, lsum0, 2);
    lsum1 += __shfl_xor_sync(0xffffffffu, lsum1, 1);
    lsum1 += __shfl_xor_sync(0xffffffffu, lsum1, 2);

    const int q0 = qt * 128 + wid * 16 + (lane >> 2);
    if ((lane & 3) == 0) {
        g_lsum[(((size_t)kz * Bn + b) * Hn + h) * Ln + q0]     = lsum0;
        g_lsum[(((size_t)kz * Bn + b) * Hn + h) * Ln + q0 + 8] = lsum1;
    }
    const size_t r0 = (((size_t)kz * Bn + b) * Ln + q0) * (Hn * Dn) + h * Dn;
    const size_t r1 = r0 + (size_t)8 * Hn * Dn;
#pragma unroll
    for (int nt = 0; nt < 16; nt++) {
        const int d = nt * 8 + (lane & 3) * 2;
        *(float2*)&g_Opart[r0 + d] = make_float2(o[nt][0], o[nt][1]);
        *(float2*)&g_Opart[r1 + d] = make_float2(o[nt][2], o[nt][3]);
    }
}

// ---------------------------------------------------------------------------
// Merge: partials add; normalize; emit tf32-rounded fp32 into g_Atf.
// ---------------------------------------------------------------------------
__global__ __launch_bounds__(256)
void merge_kernel()
{
    const size_t gid = (size_t)blockIdx.x * 256 + threadIdx.x;
    const size_t e4 = gid * 4;
    const size_t row = e4 >> 7;
    const int hh = (int)(row & (Hn - 1));
    const size_t bl = row >> 4;
    const int l = (int)(bl & (Ln - 1));
    const int b = (int)(bl >> 11);

    const float l0 = g_lsum[(((size_t)0 * Bn + b) * Hn + hh) * Ln + l];
    const float l1 = g_lsum[(((size_t)1 * Bn + b) * Hn + hh) * Ln + l];
    const float inv = 1.0f / (l0 + l1);

    const float4 vA = *(const float4*)&g_Opart[e4];
    const float4 vB = *(const float4*)&g_Opart[(size_t)Bn * Ln * Hn * Dn + e4];
    float4 r;
    r.x = tf32r((vA.x + vB.x) * inv);
    r.y = tf32r((vA.y + vB.y) * inv);
    r.z = tf32r((vA.z + vB.z) * inv);
    r.w = tf32r((vA.w + vB.w) * inv);
    *(float4*)&g_Atf[e4] = r;
}

// ---------------------------------------------------------------------------
extern "C" void kernel_launch(void* const* d_in, const int* in_sizes, int n_in,
                              void* d_out, int out_size)
{
    const float* hs = (const float*)d_in[0];
    const float* cs = (const float*)d_in[1];
    const float* sn = (const float*)d_in[2];
    const float* Wq = (const float*)d_in[3];
    const float* Wk = (const float*)d_in[4];
    const float* Wv = (const float*)d_in[5];
    const float* Wo = (const float*)d_in[6];
    const float* qw = (const float*)d_in[7];
    const float* kw = (const float*)d_in[8];
    float* out = (float*)d_out;

    cudaFuncSetAttribute(mm_kernel<true>,  cudaFuncAttributeMaxDynamicSharedMemorySize, MM_SMEM);
    cudaFuncSetAttribute(mm_kernel<false>, cudaFuncAttributeMaxDynamicSharedMemorySize, MM_SMEM);
    cudaFuncSetAttribute(attn_kernel, cudaFuncAttributeMaxDynamicSharedMemorySize, ATTN_SMEM);

    // Fused prep (tf32 rounding + weight transpose)
    prep_kernel<<<SPLIT_BLKS + TRANS_BLKS, 256>>>(hs, Wq, Wk, Wv, Wo);

    // Fused QKV projection (single-pass tf32)
    mm_kernel<true><<<dim3((Hn + 2 * KVn) * Dn / 128, (Bn * Ln) / 128), 256, MM_SMEM>>>(
        cs, sn, qw, kw, nullptr);

    // Split-K flash attention (split-bf16, fixed-max, hoisted Q) + merge
    attn_kernel<<<dim3(Ln / 128, Hn, Bn * SPLITK), 256, ATTN_SMEM>>>();
    merge_kernel<<<(Bn * Ln * Hn * Dn) / 1024, 256>>>();

    // Output projection (single-pass tf32)
    mm_kernel<false><<<dim3(HIDn / 128, (Bn * Ln) / 128), 256, MM_SMEM>>>(
        nullptr, nullptr, nullptr, nullptr, out);
}